// round 11
// baseline (speedup 1.0000x reference)
#include <cuda_runtime.h>
#include <cuda_bf16.h>
#include <math.h>

// Problem constants
#define BB 64
#define TT 256
#define HH 512
#define LL 64
#define VV 500
#define SS 3
#define NEG_INF -1000000000.0f
#define EPS_C 1e-17f

// Output section offsets (float32 elements)
#define BTH (64UL*256UL*512UL)                 // 8,388,608
#define OFF_ENCS  0UL
#define OFF_RECS  25165824UL                   // 3*BTH
#define OFF_MASKS 49741824UL                   // + 3*64*256*500
#define OFF_LOGB  49774592UL                   // + 2*16384
#define OFF_SB    49807360UL                   // + 2*16384
#define OFF_LZ    49856512UL                   // + 3*16384
#define OFF_SZ    49881088UL                   // + 3*8192

#define NBLK 128
#define NTHR 256
#define HCH 132                                // chunk row stride (floats), 132/4=33 odd
#define WS_FLOATS 8192                         // [4 j][256 k2][8]
#define HBUF_FLOATS (64*HCH)                   // 8448 per buffer
#define SMEM_USED ((WS_FLOATS + 2*HBUF_FLOATS)*4)   // 100352 B
#define SMEM_REQ  135168                       // force 1 block/SM (2x > 228KB)

// -------- device scratch (no allocation allowed) --------
__device__ float g_embW[500*2048];         // embed @ Wx
__device__ float g_embWpack[500*512*4];    // [a][j][i,f,g,o] (+bias folded)
__device__ float g_Wpack2[512*256*8];      // [j][k2][i0,i1,f0,f1,g0,g1,o0,o1]
__device__ float g_hA[64*512];
__device__ float g_hB[64*512];
__device__ float g_maskbuf[64*256];
__device__ float g_logacc[64*256];
__device__ float g_hid[16384*512];
__device__ float g_ro[64*512];
__device__ float g_hz[64*512];
__device__ float g_sz[64*64];
__device__ float g_hd[64*500 + 64*512];    // reuse region (hd uses 64*512)
__device__ float g_pred[64*500];

// barrier state: monotonic, zero-initialized, replay-safe
__device__ volatile unsigned g_arrive[NBLK*32];  // one flag per block, 128B apart
__device__ volatile unsigned g_release2;

// ---------------- helpers ----------------
__device__ __forceinline__ void ffma2(unsigned long long& d,
                                      unsigned long long a,
                                      unsigned long long b) {
    asm("fma.rn.f32x2 %0, %1, %2, %0;" : "+l"(d) : "l"(a), "l"(b));
}
__device__ __forceinline__ float lo32(unsigned long long v) {
    return __uint_as_float((unsigned)v);
}
__device__ __forceinline__ float hi32(unsigned long long v) {
    return __uint_as_float((unsigned)(v >> 32));
}
__device__ __forceinline__ float sigf(float x) { return 1.f / (1.f + expf(-x)); }

struct ull2 { unsigned long long x, y; };

__device__ __forceinline__ void cp16(float* s, const float* g) {
    unsigned sa = (unsigned)__cvta_generic_to_shared(s);
    asm volatile("cp.async.cg.shared.global [%0], [%1], 16;" :: "r"(sa), "l"(g));
}
__device__ __forceinline__ void cp_commit() {
    asm volatile("cp.async.commit_group;" ::: "memory");
}
template <int N>
__device__ __forceinline__ void cp_waitg() {
    asm volatile("cp.async.wait_group %0;" :: "n"(N) : "memory");
}

// load chunk c (k in [128c, 128c+128)) of cur h into buf
__device__ __forceinline__ void load_chunk(float* __restrict__ buf,
                                           const float* __restrict__ cur,
                                           int c, int tid) {
#pragma unroll
    for (int it = 0; it < 8; it++) {
        int i = tid + (it << 8);
        int r = i >> 5;
        int kq = i & 31;
        cp16(buf + r*HCH + (kq << 2), cur + (r << 9) + (c << 7) + (kq << 2));
    }
    cp_commit();
}

// compute 32 k4 iterations of one chunk
__device__ __forceinline__ void comp_chunk(const float* __restrict__ hrow,
                                           const float* __restrict__ wc,
                                           unsigned long long& ai, unsigned long long& af,
                                           unsigned long long& ag, unsigned long long& ao) {
#pragma unroll
    for (int k4 = 0; k4 < 32; k4++) {
        ull2 h4 = *(const ull2*)(hrow + (k4 << 2));
        const float* wk = wc + (k4 << 4);
        ull2 wA = *(const ull2*)(wk);
        ull2 wB = *(const ull2*)(wk + 4);
        ull2 wC = *(const ull2*)(wk + 8);
        ull2 wD = *(const ull2*)(wk + 12);
        ffma2(ai, h4.x, wA.x); ffma2(af, h4.x, wA.y);
        ffma2(ag, h4.x, wB.x); ffma2(ao, h4.x, wB.y);
        ffma2(ai, h4.y, wC.x); ffma2(af, h4.y, wC.y);
        ffma2(ag, h4.y, wD.x); ffma2(ao, h4.y, wD.y);
    }
}

// grid barrier: arrive flags + block-0 gather + release broadcast
__device__ __forceinline__ void seg_barrier(unsigned target) {
    __threadfence();
    __syncthreads();
    if (threadIdx.x == 0)
        g_arrive[blockIdx.x * 32] = target;
    if (blockIdx.x == 0) {
        if (threadIdx.x < NBLK) {
            while ((int)(g_arrive[threadIdx.x * 32] - target) < 0) __nanosleep(20);
        }
        __syncthreads();
        if (threadIdx.x == 0) { __threadfence(); g_release2 = target; }
    }
    if (threadIdx.x == 0) {
        while ((int)(g_release2 - target) < 0) __nanosleep(20);
    }
    __threadfence();
    __syncthreads();
}

// ---------------- persistent masked-LSTM segment kernel ----------------
// 128 blocks x 256 threads. block -> 4 j; warp -> (jj = wid>>1, half = wid&1);
// thread -> one (b, j), 4 gates.
__global__ __launch_bounds__(NTHR, 1) void lstm_seg_k(
    const int* __restrict__ actions,
    const float* __restrict__ maskp,   // nullptr for seg 0
    float* __restrict__ enc)
{
    extern __shared__ float smem[];
    float* ws  = smem;                       // [4][256][8]
    float* hb0 = smem + WS_FLOATS;           // [64][HCH]
    float* hb1 = hb0 + HBUF_FLOATS;

    const int tid  = threadIdx.x;
    const int lane = tid & 31;
    const int wid  = tid >> 5;
    const int jj   = wid >> 1;
    const int j    = (blockIdx.x << 2) | jj;
    const int b    = ((wid & 1) << 5) | lane;

    // stage this block's Wh pack (constant across steps)
    {
        const float4* src = (const float4*)(g_Wpack2 + (size_t)blockIdx.x * 8192);
        float4* dst = (float4*)ws;
#pragma unroll
        for (int i = tid; i < 2048; i += NTHR) dst[i] = src[i];
    }
    __syncthreads();

    const unsigned base = g_release2;        // stable between launches
    const int useMask = (maskp != nullptr);
    const float* wj = ws + (jj << 11);       // 2048 floats per j
    const float* hr0 = hb0 + b * HCH;
    const float* hr1 = hb1 + b * HCH;
    float c = 0.f;

    for (int t = 0; t < TT; t++) {
        float zi = 0.f, zf = 0.f, zg = 0.f, zo = 0.f;

        if (t > 0) {
            const float* cur = (t & 1) ? g_hA : g_hB;   // h(t-1)
            load_chunk(hb0, cur, 0, tid);
            load_chunk(hb1, cur, 1, tid);

            unsigned long long ai = 0, af = 0, ag = 0, ao = 0;

            cp_waitg<1>(); __syncthreads();
            comp_chunk(hr0, wj + 0*512, ai, af, ag, ao);
            __syncthreads();
            load_chunk(hb0, cur, 2, tid);

            cp_waitg<1>(); __syncthreads();
            comp_chunk(hr1, wj + 1*512, ai, af, ag, ao);
            __syncthreads();
            load_chunk(hb1, cur, 3, tid);

            cp_waitg<1>(); __syncthreads();
            comp_chunk(hr0, wj + 2*512, ai, af, ag, ao);

            cp_waitg<0>(); __syncthreads();
            comp_chunk(hr1, wj + 3*512, ai, af, ag, ao);

            zi = lo32(ai) + hi32(ai);
            zf = lo32(af) + hi32(af);
            zg = lo32(ag) + hi32(ag);
            zo = lo32(ao) + hi32(ao);
        }

        int act = actions[b * TT + t];
        float4 x = *(const float4*)(g_embWpack + (((size_t)act << 9) + j) * 4);
        zi += x.x; zf += x.y; zg += x.z; zo += x.w;

        float cn = sigf(zf) * c + sigf(zi) * tanhf(zg);
        float hn = sigf(zo) * tanhf(cn);

        enc[((size_t)b * TT + t) * HH + j] = hn;

        float m = useMask ? maskp[b * TT + t] : 1.f;
        c = m * cn;
        float* nxt = (t & 1) ? g_hB : g_hA;
        nxt[(b << 9) + j] = m * hn;

        if (t < TT - 1) seg_barrier(base + t + 1);
    }
}

// ---------------- pack kernels ----------------
__global__ void pack_embW_k(const float* __restrict__ b_lstm) {
    int a = blockIdx.x;         // 0..499
    int j = threadIdx.x;        // 0..511
    float4 v;
    v.x = g_embW[(size_t)a*2048 +        j] + b_lstm[j];
    v.y = g_embW[(size_t)a*2048 +  512 + j] + b_lstm[512 + j];
    v.z = g_embW[(size_t)a*2048 + 1024 + j] + b_lstm[1024 + j];
    v.w = g_embW[(size_t)a*2048 + 1536 + j] + b_lstm[1536 + j];
    *(float4*)(g_embWpack + ((size_t)a*512 + j)*4) = v;
}

// pack Wh into [j][k2][i0,i1,f0,f1,g0,g1,o0,o1]
__global__ void pack_Wh2_k(const float* __restrict__ Wh) {
    int idx = blockIdx.x * blockDim.x + threadIdx.x;   // 131072
    if (idx >= 512*256) return;
    int j  = idx >> 8;
    int k2 = idx & 255;
    float v[8];
#pragma unroll
    for (int g = 0; g < 4; g++) {
#pragma unroll
        for (int p = 0; p < 2; p++)
            v[g*2 + p] = Wh[(size_t)(2*k2 + p)*2048 + g*512 + j];
    }
    float4* dst = (float4*)(g_Wpack2 + ((size_t)j*256 + k2)*8);
    dst[0] = make_float4(v[0], v[1], v[2], v[3]);
    dst[1] = make_float4(v[4], v[5], v[6], v[7]);
}

// ---------------- generic tiled SGEMM ----------------
#define BM 64
#define BN 64
#define BKT 32
__global__ __launch_bounds__(256) void sgemm_k(
    const float* __restrict__ A, int lda,
    const float* __restrict__ B, int ldb,
    float* __restrict__ C, int ldc,
    int M, int N, int K,
    const float* __restrict__ bias, int relu)
{
    __shared__ float As[BKT][BM + 1];
    __shared__ float Bs[BKT][BN];

    int m0 = blockIdx.y * BM;
    int n0 = blockIdx.x * BN;
    int tid = threadIdx.x;
    int tx = tid & 15;
    int ty = tid >> 4;

    float acc[4][4];
#pragma unroll
    for (int i = 0; i < 4; i++)
#pragma unroll
        for (int jq = 0; jq < 4; jq++) acc[i][jq] = 0.f;

    for (int k0 = 0; k0 < K; k0 += BKT) {
#pragma unroll
        for (int i = 0; i < (BM*BKT)/256; i++) {
            int idx = tid + i*256;
            int m  = idx >> 5;
            int kk = idx & 31;
            int gm = m0 + m;
            As[kk][m] = (gm < M) ? A[(size_t)gm*lda + k0 + kk] : 0.f;
        }
#pragma unroll
        for (int i = 0; i < (BKT*BN)/256; i++) {
            int idx = tid + i*256;
            int kk = idx >> 6;
            int n  = idx & 63;
            int gn = n0 + n;
            Bs[kk][n] = (gn < N) ? B[(size_t)(k0+kk)*ldb + gn] : 0.f;
        }
        __syncthreads();
#pragma unroll
        for (int kk = 0; kk < BKT; kk++) {
            float a0 = As[kk][ty*4+0];
            float a1 = As[kk][ty*4+1];
            float a2 = As[kk][ty*4+2];
            float a3 = As[kk][ty*4+3];
            float4 b4 = *(const float4*)&Bs[kk][tx*4];
            acc[0][0] += a0*b4.x; acc[0][1] += a0*b4.y; acc[0][2] += a0*b4.z; acc[0][3] += a0*b4.w;
            acc[1][0] += a1*b4.x; acc[1][1] += a1*b4.y; acc[1][2] += a1*b4.z; acc[1][3] += a1*b4.w;
            acc[2][0] += a2*b4.x; acc[2][1] += a2*b4.y; acc[2][2] += a2*b4.z; acc[2][3] += a2*b4.w;
            acc[3][0] += a3*b4.x; acc[3][1] += a3*b4.y; acc[3][2] += a3*b4.z; acc[3][3] += a3*b4.w;
        }
        __syncthreads();
    }

#pragma unroll
    for (int i = 0; i < 4; i++) {
        int gm = m0 + ty*4 + i;
        if (gm >= M) continue;
#pragma unroll
        for (int jq = 0; jq < 4; jq++) {
            int gn = n0 + tx*4 + jq;
            if (gn >= N) continue;
            float v = acc[i][jq];
            if (bias) v += bias[gn];
            if (relu) v = fmaxf(v, 0.f);
            C[(size_t)gm*ldc + gn] = v;
        }
    }
}

// ---------------- small helpers ----------------
__global__ void zero1_k(float* a, int n) {
    int i = blockIdx.x * blockDim.x + threadIdx.x;
    if (i < n) a[i] = 0.f;
}

__global__ __launch_bounds__(256) void rowdot_k(
    const float* __restrict__ hid, const float* __restrict__ Wb2,
    const float* __restrict__ bb2, float* __restrict__ logits_out)
{
    int row  = blockIdx.x * 8 + (threadIdx.x >> 5);
    int lane = threadIdx.x & 31;
    const float* hr = hid + (size_t)row * 512;
    float acc = 0.f;
#pragma unroll
    for (int i = lane; i < 512; i += 32) acc += hr[i] * Wb2[i];
#pragma unroll
    for (int o = 16; o > 0; o >>= 1) acc += __shfl_down_sync(0xffffffffu, acc, o);
    if (lane == 0) {
        float v = acc + bb2[0];
        if ((row & 255) == 0) v = NEG_INF;
        logits_out[row] = v;
    }
}

__global__ __launch_bounds__(256) void softmax_mask_k(
    const float* __restrict__ logits, const float* __restrict__ gumbel,
    float* __restrict__ sb_out, float* __restrict__ mask_out,
    float* __restrict__ maskbuf, float* __restrict__ logacc)
{
    int b = blockIdx.x;
    int t = threadIdx.x;
    __shared__ float sh[256];

    float x = logits[b*TT + t] + gumbel[b*TT + t];
    sh[t] = x; __syncthreads();
    for (int s = 128; s > 0; s >>= 1) { if (t < s) sh[t] = fmaxf(sh[t], sh[t+s]); __syncthreads(); }
    float mx = sh[0]; __syncthreads();

    float e = expf(x - mx);
    sh[t] = e; __syncthreads();
    for (int s = 128; s > 0; s >>= 1) { if (t < s) sh[t] += sh[t+s]; __syncthreads(); }
    float sum = sh[0]; __syncthreads();

    float p = e / sum;
    sb_out[b*TT + t] = p;

    sh[t] = p; __syncthreads();
    for (int off = 1; off < 256; off <<= 1) {
        float v = (t >= off) ? sh[t - off] : 0.f;
        __syncthreads();
        sh[t] += v;
        __syncthreads();
    }
    float cum = sh[t];
    float la = logacc[b*TT + t] + logf(cum + EPS_C);
    logacc[b*TT + t] = la;
    float m = expf(la);
    maskbuf[b*TT + t] = m;
    mask_out[b*TT + t] = m;
}

__global__ void onehot_k(const int* __restrict__ lengths, float* __restrict__ sb_out) {
    int b = blockIdx.x, t = threadIdx.x;
    sb_out[b*TT + t] = (t == lengths[b] - 1) ? 1.f : 0.f;
}

__global__ __launch_bounds__(512) void readout_k(
    const float* __restrict__ enc, const float* __restrict__ sb,
    float* __restrict__ ro)
{
    int b = blockIdx.x;
    int h = threadIdx.x;
    __shared__ float s_sb[256];
    if (h < 256) s_sb[h] = sb[b*TT + h];
    __syncthreads();
    const float* e = enc + (size_t)b*TT*HH;
    float acc = 0.f;
    for (int t = 0; t < TT - 1; t++)
        acc += e[(size_t)t*HH + h] * s_sb[t + 1];
    ro[b*HH + h] = acc;
}

__global__ void samplez_k(const float* __restrict__ lz, const float* __restrict__ eps,
                          float* __restrict__ sz_out, float* __restrict__ szbuf)
{
    int id = blockIdx.x * blockDim.x + threadIdx.x;
    int b = id >> 6, l = id & 63;
    float mu = lz[b*128 + l];
    float lv = lz[b*128 + 64 + l];
    float v = mu + expf(0.5f * lv) * eps[b*64 + l];
    sz_out[id] = v;
    szbuf[id]  = v;
}

__global__ __launch_bounds__(256) void recs_k(const float* __restrict__ pred,
                                              float* __restrict__ out)
{
    long idx = (long)blockIdx.x * 256 + threadIdx.x;
    if (idx >= (long)BB*TT*VV) return;
    int v = (int)(idx % VV);
    int b = (int)(idx / ((long)VV * TT));
    out[idx] = pred[b*VV + v];
}

// ---------------- host orchestration ----------------
extern "C" void kernel_launch(void* const* d_in, const int* in_sizes, int n_in,
                              void* d_out, int out_size)
{
    const int*   actions = (const int*)  d_in[0];
    const int*   lengths = (const int*)  d_in[1];
    const float* gumbel  = (const float*)d_in[2];
    const float* eps_z   = (const float*)d_in[3];
    const float* embed   = (const float*)d_in[4];
    const float* Wx      = (const float*)d_in[5];
    const float* Wh      = (const float*)d_in[6];
    const float* b_lstm  = (const float*)d_in[7];
    const float* Wz1     = (const float*)d_in[8];
    const float* bz1     = (const float*)d_in[9];
    const float* Wz2     = (const float*)d_in[10];
    const float* bz2     = (const float*)d_in[11];
    const float* Wb1     = (const float*)d_in[12];
    const float* bb1     = (const float*)d_in[13];
    const float* Wb2     = (const float*)d_in[14];
    const float* bb2     = (const float*)d_in[15];
    const float* Wd1     = (const float*)d_in[16];
    const float* bd1     = (const float*)d_in[17];
    const float* Wd2     = (const float*)d_in[18];
    const float* bd2     = (const float*)d_in[19];
    float* out = (float*)d_out;

    float *p_embW, *p_mask, *p_logacc, *p_hid, *p_ro, *p_hz, *p_sz, *p_hd, *p_pred;
    cudaGetSymbolAddress((void**)&p_embW,   g_embW);
    cudaGetSymbolAddress((void**)&p_mask,   g_maskbuf);
    cudaGetSymbolAddress((void**)&p_logacc, g_logacc);
    cudaGetSymbolAddress((void**)&p_hid,    g_hid);
    cudaGetSymbolAddress((void**)&p_ro,     g_ro);
    cudaGetSymbolAddress((void**)&p_hz,     g_hz);
    cudaGetSymbolAddress((void**)&p_sz,     g_sz);
    cudaGetSymbolAddress((void**)&p_hd,     g_hd);
    cudaGetSymbolAddress((void**)&p_pred,   g_pred);

    cudaFuncSetAttribute(lstm_seg_k, cudaFuncAttributeMaxDynamicSharedMemorySize,
                         SMEM_REQ);

    // embW = embed @ Wx   (500 x 2048, K=512)
    sgemm_k<<<dim3(32, 8, 1), 256>>>(embed, 512, Wx, 2048, p_embW, 2048,
                                     500, 2048, 512, nullptr, 0);
    pack_embW_k<<<500, 512>>>(b_lstm);
    pack_Wh2_k<<<512, 256>>>(Wh);
    zero1_k<<<64, 256>>>(p_logacc, BB*TT);

    for (int seg = 0; seg < SS; seg++) {
        float* enc = out + OFF_ENCS + (size_t)seg * BTH;
        const float* mptr = (seg == 0) ? nullptr : p_mask;

        lstm_seg_k<<<NBLK, NTHR, SMEM_REQ>>>(actions, mptr, enc);

        if (seg < SS - 1) {
            sgemm_k<<<dim3(8, 256, 1), 256>>>(enc, 512, Wb1, 512, p_hid, 512,
                                              16384, 512, 512, bb1, 1);
            rowdot_k<<<2048, 256>>>(p_hid, Wb2, bb2, out + OFF_LOGB + (size_t)seg*BB*TT);
            softmax_mask_k<<<64, 256>>>(out + OFF_LOGB + (size_t)seg*BB*TT,
                                        gumbel + (size_t)seg*BB*TT,
                                        out + OFF_SB + (size_t)seg*BB*TT,
                                        out + OFF_MASKS + (size_t)seg*BB*TT,
                                        p_mask, p_logacc);
        } else {
            onehot_k<<<64, 256>>>(lengths, out + OFF_SB + (size_t)seg*BB*TT);
        }

        readout_k<<<64, 512>>>(enc, out + OFF_SB + (size_t)seg*BB*TT, p_ro);

        sgemm_k<<<dim3(8, 1, 1), 256>>>(p_ro, 512, Wz1, 512, p_hz, 512,
                                        64, 512, 512, bz1, 1);
        sgemm_k<<<dim3(2, 1, 1), 256>>>(p_hz, 512, Wz2, 128,
                                        out + OFF_LZ + (size_t)seg*BB*2*LL, 128,
                                        64, 128, 512, bz2, 0);
        samplez_k<<<16, 256>>>(out + OFF_LZ + (size_t)seg*BB*2*LL,
                               eps_z + (size_t)seg*BB*LL,
                               out + OFF_SZ + (size_t)seg*BB*LL, p_sz);
        sgemm_k<<<dim3(8, 1, 1), 256>>>(p_sz, 64, Wd1, 512, p_hd, 512,
                                        64, 512, 64, bd1, 1);
        sgemm_k<<<dim3(8, 1, 1), 256>>>(p_hd, 512, Wd2, 500, p_pred, 500,
                                        64, 500, 512, bd2, 0);
        recs_k<<<32000, 256>>>(p_pred, out + OFF_RECS + (size_t)seg*(size_t)BB*TT*VV);
    }
}

// round 12
// speedup vs baseline: 1.0606x; 1.0606x over previous
#include <cuda_runtime.h>
#include <cuda_bf16.h>
#include <math.h>

// Problem constants
#define BB 64
#define TT 256
#define HH 512
#define LL 64
#define VV 500
#define SS 3
#define NEG_INF -1000000000.0f
#define EPS_C 1e-17f

// Output section offsets (float32 elements)
#define BTH (64UL*256UL*512UL)                 // 8,388,608
#define OFF_ENCS  0UL
#define OFF_RECS  25165824UL                   // 3*BTH
#define OFF_MASKS 49741824UL                   // + 3*64*256*500
#define OFF_LOGB  49774592UL                   // + 2*16384
#define OFF_SB    49807360UL                   // + 2*16384
#define OFF_LZ    49856512UL                   // + 3*16384
#define OFF_SZ    49881088UL                   // + 3*8192

#define NBLK 128
#define NTHR 256
#define HROW 516                               // padded h row stride (floats)
#define WS_FLOATS 8192                         // [4 j][256 k2][8]
#define H_FLOATS  (64*HROW)                    // 33024
#define RB_FLOATS (4*32*20)                    // 2560 (stride 20 = 80B, 16B aligned)
#define SMEM_FLOATS (WS_FLOATS + H_FLOATS + RB_FLOATS)   // 43776
#define SMEM_BYTES  (SMEM_FLOATS*4)            // 175104 -> 1 block/SM

// -------- device scratch (no allocation allowed) --------
__device__ float g_embW[500*2048];         // embed @ Wx
__device__ float g_embWpack[500*512*4];    // [a][j][i,f,g,o] (+bias folded)
__device__ float g_Wpack2[512*256*8];      // [j][k2][i0,i1,f0,f1,g0,g1,o0,o1]
__device__ float g_hA[64*512];
__device__ float g_hB[64*512];
__device__ float g_maskbuf[64*256];
__device__ float g_logacc[64*256];
__device__ float g_hid[16384*512];
__device__ float g_ro[64*512];
__device__ float g_hz[64*512];
__device__ float g_sz[64*64];
__device__ float g_hd[64*512];
__device__ float g_pred[64*500];

// barrier state: monotonic, zero-init, replay-safe
__device__ volatile unsigned g_bar_flag;
__device__ unsigned g_bar_count;

// ---------------- helpers ----------------
__device__ __forceinline__ void ffma2(unsigned long long& d,
                                      unsigned long long a,
                                      unsigned long long b) {
    asm("fma.rn.f32x2 %0, %1, %2, %0;" : "+l"(d) : "l"(a), "l"(b));
}
__device__ __forceinline__ float lo32(unsigned long long v) {
    return __uint_as_float((unsigned)v);
}
__device__ __forceinline__ float hi32(unsigned long long v) {
    return __uint_as_float((unsigned)(v >> 32));
}
__device__ __forceinline__ float sigf(float x) { return 1.f / (1.f + expf(-x)); }

struct ull2 { unsigned long long x, y; };

__device__ __forceinline__ void cp16(float* s, const float* g) {
    unsigned sa = (unsigned)__cvta_generic_to_shared(s);
    asm volatile("cp.async.cg.shared.global [%0], [%1], 16;" :: "r"(sa), "l"(g));
}
__device__ __forceinline__ void cp_commit() {
    asm volatile("cp.async.commit_group;" ::: "memory");
}
template <int N>
__device__ __forceinline__ void cp_waitg() {
    asm volatile("cp.async.wait_group %0;" :: "n"(N) : "memory");
}

// grid-wide spin barrier (no nanosleep), single-owner release
__device__ __forceinline__ void grid_barrier(unsigned& barBase) {
    __threadfence();
    __syncthreads();
    if (threadIdx.x == 0) {
        barBase++;
        unsigned old = atomicAdd(&g_bar_count, 1);
        if (old == NBLK - 1) {
            g_bar_count = 0;
            __threadfence();
            g_bar_flag = barBase;
        } else {
            while ((int)(g_bar_flag - barBase) < 0) { }   // pure spin on L2 line
        }
        __threadfence();
    }
    __syncthreads();
}

// ---------------- persistent masked-LSTM segment kernel ----------------
// 128 blocks x 256 threads. warp = (jj = wid>>1, khalf = wid&1);
// thread -> (b=lane, b+32) x j, its 256-k half. kh=1 warps dump partials to
// smem; kh=0 warps combine + gates + writes.
__global__ __launch_bounds__(NTHR, 1) void lstm_seg_k(
    const int* __restrict__ actions,
    const float* __restrict__ maskp,   // nullptr for seg 0
    float* __restrict__ enc)
{
    extern __shared__ float smem[];
    float* ws = smem;                       // [4][256][8]
    float* hs = smem + WS_FLOATS;           // [64][HROW]
    float* rb = hs + H_FLOATS;              // [4*32][20]

    const int tid  = threadIdx.x;
    const int lane = tid & 31;
    const int wid  = tid >> 5;
    const int jj   = wid >> 1;
    const int kh   = wid & 1;
    const int j    = (blockIdx.x << 2) | jj;
    const int b1   = lane;
    const int b2   = lane + 32;

    // stage this block's Wh pack (constant across steps)
    {
        const float4* src = (const float4*)(g_Wpack2 + (size_t)blockIdx.x * 8192);
        float4* dst = (float4*)ws;
#pragma unroll
        for (int i = tid; i < 2048; i += NTHR) dst[i] = src[i];
    }
    __syncthreads();

    unsigned barBase = g_bar_flag;          // stable at kernel entry
    const int useMask = (maskp != nullptr);
    const float* wj  = ws + (jj << 11) + (kh << 10);
    const float* hp1 = hs + b1 * HROW + (kh << 8);
    const float* hp2 = hs + b2 * HROW + (kh << 8);
    float* myrb = rb + (jj * 32 + lane) * 20;
    float c1 = 0.f, c2 = 0.f;

    for (int t = 0; t < TT; t++) {
        unsigned long long a0=0,a1=0,a2=0,a3=0,a4=0,a5=0,a6=0,a7=0;

        if (t > 0) {
            const float* cur = (t & 1) ? g_hA : g_hB;   // h(t-1)
            // stage full h -> smem (32 cp16 per thread)
#pragma unroll
            for (int it = 0; it < 32; it++) {
                int i = tid + (it << 8);
                int r = i >> 7;
                int q = i & 127;
                cp16(hs + r * HROW + (q << 2), cur + (r << 9) + (q << 2));
            }
            cp_commit();
            cp_waitg<0>();
            __syncthreads();

#pragma unroll 4
            for (int k4 = 0; k4 < 64; k4++) {
                ull2 ha = *(const ull2*)(hp1 + (k4 << 2));
                ull2 hb = *(const ull2*)(hp2 + (k4 << 2));
                const float* wk = wj + (k4 << 4);
                ull2 wA = *(const ull2*)(wk);
                ull2 wB = *(const ull2*)(wk + 4);
                ull2 wC = *(const ull2*)(wk + 8);
                ull2 wD = *(const ull2*)(wk + 12);
                ffma2(a0, ha.x, wA.x); ffma2(a1, ha.x, wA.y);
                ffma2(a2, ha.x, wB.x); ffma2(a3, ha.x, wB.y);
                ffma2(a0, ha.y, wC.x); ffma2(a1, ha.y, wC.y);
                ffma2(a2, ha.y, wD.x); ffma2(a3, ha.y, wD.y);
                ffma2(a4, hb.x, wA.x); ffma2(a5, hb.x, wA.y);
                ffma2(a6, hb.x, wB.x); ffma2(a7, hb.x, wB.y);
                ffma2(a4, hb.y, wC.x); ffma2(a5, hb.y, wC.y);
                ffma2(a6, hb.y, wD.x); ffma2(a7, hb.y, wD.y);
            }

            if (kh) {   // dump partials for the combiner warp
                ull2* p = (ull2*)myrb;
                p[0].x = a0; p[0].y = a1;
                p[1].x = a2; p[1].y = a3;
                p[2].x = a4; p[2].y = a5;
                p[3].x = a6; p[3].y = a7;
            }
            __syncthreads();
        }

        if (kh == 0) {
            float zi1, zf1, zg1, zo1, zi2, zf2, zg2, zo2;
            if (t > 0) {
                const ull2* p = (const ull2*)myrb;
                ull2 p0 = p[0], p1 = p[1], p2 = p[2], p3 = p[3];
                zi1 = lo32(a0)+hi32(a0) + lo32(p0.x)+hi32(p0.x);
                zf1 = lo32(a1)+hi32(a1) + lo32(p0.y)+hi32(p0.y);
                zg1 = lo32(a2)+hi32(a2) + lo32(p1.x)+hi32(p1.x);
                zo1 = lo32(a3)+hi32(a3) + lo32(p1.y)+hi32(p1.y);
                zi2 = lo32(a4)+hi32(a4) + lo32(p2.x)+hi32(p2.x);
                zf2 = lo32(a5)+hi32(a5) + lo32(p2.y)+hi32(p2.y);
                zg2 = lo32(a6)+hi32(a6) + lo32(p3.x)+hi32(p3.x);
                zo2 = lo32(a7)+hi32(a7) + lo32(p3.y)+hi32(p3.y);
            } else {
                zi1=zf1=zg1=zo1=zi2=zf2=zg2=zo2 = 0.f;
            }

            int act1 = actions[b1 * TT + t];
            int act2 = actions[b2 * TT + t];
            float4 x1 = *(const float4*)(g_embWpack + (((size_t)act1 << 9) + j) * 4);
            float4 x2 = *(const float4*)(g_embWpack + (((size_t)act2 << 9) + j) * 4);
            zi1 += x1.x; zf1 += x1.y; zg1 += x1.z; zo1 += x1.w;
            zi2 += x2.x; zf2 += x2.y; zg2 += x2.z; zo2 += x2.w;

            float c1n = sigf(zf1) * c1 + sigf(zi1) * tanhf(zg1);
            float h1n = sigf(zo1) * tanhf(c1n);
            float c2n = sigf(zf2) * c2 + sigf(zi2) * tanhf(zg2);
            float h2n = sigf(zo2) * tanhf(c2n);

            enc[((size_t)b1 * TT + t) * HH + j] = h1n;
            enc[((size_t)b2 * TT + t) * HH + j] = h2n;

            float m1 = useMask ? maskp[b1 * TT + t] : 1.f;
            float m2 = useMask ? maskp[b2 * TT + t] : 1.f;
            c1 = m1 * c1n;
            c2 = m2 * c2n;
            float* nxt = (t & 1) ? g_hB : g_hA;
            nxt[(b1 << 9) + j] = m1 * h1n;
            nxt[(b2 << 9) + j] = m2 * h2n;
        }

        if (t < TT - 1) grid_barrier(barBase);
    }
}

// ---------------- pack kernels ----------------
__global__ void pack_embW_k(const float* __restrict__ b_lstm) {
    int a = blockIdx.x;         // 0..499
    int j = threadIdx.x;        // 0..511
    float4 v;
    v.x = g_embW[(size_t)a*2048 +        j] + b_lstm[j];
    v.y = g_embW[(size_t)a*2048 +  512 + j] + b_lstm[512 + j];
    v.z = g_embW[(size_t)a*2048 + 1024 + j] + b_lstm[1024 + j];
    v.w = g_embW[(size_t)a*2048 + 1536 + j] + b_lstm[1536 + j];
    *(float4*)(g_embWpack + ((size_t)a*512 + j)*4) = v;
}

// pack Wh into [j][k2][i0,i1,f0,f1,g0,g1,o0,o1]
__global__ void pack_Wh2_k(const float* __restrict__ Wh) {
    int idx = blockIdx.x * blockDim.x + threadIdx.x;   // 131072
    if (idx >= 512*256) return;
    int j  = idx >> 8;
    int k2 = idx & 255;
    float v[8];
#pragma unroll
    for (int g = 0; g < 4; g++) {
#pragma unroll
        for (int p = 0; p < 2; p++)
            v[g*2 + p] = Wh[(size_t)(2*k2 + p)*2048 + g*512 + j];
    }
    float4* dst = (float4*)(g_Wpack2 + ((size_t)j*256 + k2)*8);
    dst[0] = make_float4(v[0], v[1], v[2], v[3]);
    dst[1] = make_float4(v[4], v[5], v[6], v[7]);
}

// ---------------- generic tiled SGEMM ----------------
#define BM 64
#define BN 64
#define BKT 32
__global__ __launch_bounds__(256) void sgemm_k(
    const float* __restrict__ A, int lda,
    const float* __restrict__ B, int ldb,
    float* __restrict__ C, int ldc,
    int M, int N, int K,
    const float* __restrict__ bias, int relu)
{
    __shared__ float As[BKT][BM + 1];
    __shared__ float Bs[BKT][BN];

    int m0 = blockIdx.y * BM;
    int n0 = blockIdx.x * BN;
    int tid = threadIdx.x;
    int tx = tid & 15;
    int ty = tid >> 4;

    float acc[4][4];
#pragma unroll
    for (int i = 0; i < 4; i++)
#pragma unroll
        for (int jq = 0; jq < 4; jq++) acc[i][jq] = 0.f;

    for (int k0 = 0; k0 < K; k0 += BKT) {
#pragma unroll
        for (int i = 0; i < (BM*BKT)/256; i++) {
            int idx = tid + i*256;
            int m  = idx >> 5;
            int kk = idx & 31;
            int gm = m0 + m;
            As[kk][m] = (gm < M) ? A[(size_t)gm*lda + k0 + kk] : 0.f;
        }
#pragma unroll
        for (int i = 0; i < (BKT*BN)/256; i++) {
            int idx = tid + i*256;
            int kk = idx >> 6;
            int n  = idx & 63;
            int gn = n0 + n;
            Bs[kk][n] = (gn < N) ? B[(size_t)(k0+kk)*ldb + gn] : 0.f;
        }
        __syncthreads();
#pragma unroll
        for (int kk = 0; kk < BKT; kk++) {
            float a0 = As[kk][ty*4+0];
            float a1 = As[kk][ty*4+1];
            float a2 = As[kk][ty*4+2];
            float a3 = As[kk][ty*4+3];
            float4 b4 = *(const float4*)&Bs[kk][tx*4];
            acc[0][0] += a0*b4.x; acc[0][1] += a0*b4.y; acc[0][2] += a0*b4.z; acc[0][3] += a0*b4.w;
            acc[1][0] += a1*b4.x; acc[1][1] += a1*b4.y; acc[1][2] += a1*b4.z; acc[1][3] += a1*b4.w;
            acc[2][0] += a2*b4.x; acc[2][1] += a2*b4.y; acc[2][2] += a2*b4.z; acc[2][3] += a2*b4.w;
            acc[3][0] += a3*b4.x; acc[3][1] += a3*b4.y; acc[3][2] += a3*b4.z; acc[3][3] += a3*b4.w;
        }
        __syncthreads();
    }

#pragma unroll
    for (int i = 0; i < 4; i++) {
        int gm = m0 + ty*4 + i;
        if (gm >= M) continue;
#pragma unroll
        for (int jq = 0; jq < 4; jq++) {
            int gn = n0 + tx*4 + jq;
            if (gn >= N) continue;
            float v = acc[i][jq];
            if (bias) v += bias[gn];
            if (relu) v = fmaxf(v, 0.f);
            C[(size_t)gm*ldc + gn] = v;
        }
    }
}

// ---------------- small helpers ----------------
__global__ void zero1_k(float* a, int n) {
    int i = blockIdx.x * blockDim.x + threadIdx.x;
    if (i < n) a[i] = 0.f;
}

__global__ __launch_bounds__(256) void rowdot_k(
    const float* __restrict__ hid, const float* __restrict__ Wb2,
    const float* __restrict__ bb2, float* __restrict__ logits_out)
{
    int row  = blockIdx.x * 8 + (threadIdx.x >> 5);
    int lane = threadIdx.x & 31;
    const float* hr = hid + (size_t)row * 512;
    float acc = 0.f;
#pragma unroll
    for (int i = lane; i < 512; i += 32) acc += hr[i] * Wb2[i];
#pragma unroll
    for (int o = 16; o > 0; o >>= 1) acc += __shfl_down_sync(0xffffffffu, acc, o);
    if (lane == 0) {
        float v = acc + bb2[0];
        if ((row & 255) == 0) v = NEG_INF;
        logits_out[row] = v;
    }
}

__global__ __launch_bounds__(256) void softmax_mask_k(
    const float* __restrict__ logits, const float* __restrict__ gumbel,
    float* __restrict__ sb_out, float* __restrict__ mask_out,
    float* __restrict__ maskbuf, float* __restrict__ logacc)
{
    int b = blockIdx.x;
    int t = threadIdx.x;
    __shared__ float sh[256];

    float x = logits[b*TT + t] + gumbel[b*TT + t];
    sh[t] = x; __syncthreads();
    for (int s = 128; s > 0; s >>= 1) { if (t < s) sh[t] = fmaxf(sh[t], sh[t+s]); __syncthreads(); }
    float mx = sh[0]; __syncthreads();

    float e = expf(x - mx);
    sh[t] = e; __syncthreads();
    for (int s = 128; s > 0; s >>= 1) { if (t < s) sh[t] += sh[t+s]; __syncthreads(); }
    float sum = sh[0]; __syncthreads();

    float p = e / sum;
    sb_out[b*TT + t] = p;

    sh[t] = p; __syncthreads();
    for (int off = 1; off < 256; off <<= 1) {
        float v = (t >= off) ? sh[t - off] : 0.f;
        __syncthreads();
        sh[t] += v;
        __syncthreads();
    }
    float cum = sh[t];
    float la = logacc[b*TT + t] + logf(cum + EPS_C);
    logacc[b*TT + t] = la;
    float m = expf(la);
    maskbuf[b*TT + t] = m;
    mask_out[b*TT + t] = m;
}

__global__ void onehot_k(const int* __restrict__ lengths, float* __restrict__ sb_out) {
    int b = blockIdx.x, t = threadIdx.x;
    sb_out[b*TT + t] = (t == lengths[b] - 1) ? 1.f : 0.f;
}

__global__ __launch_bounds__(512) void readout_k(
    const float* __restrict__ enc, const float* __restrict__ sb,
    float* __restrict__ ro)
{
    int b = blockIdx.x;
    int h = threadIdx.x;
    __shared__ float s_sb[256];
    if (h < 256) s_sb[h] = sb[b*TT + h];
    __syncthreads();
    const float* e = enc + (size_t)b*TT*HH;
    float acc = 0.f;
    for (int t = 0; t < TT - 1; t++)
        acc += e[(size_t)t*HH + h] * s_sb[t + 1];
    ro[b*HH + h] = acc;
}

__global__ void samplez_k(const float* __restrict__ lz, const float* __restrict__ eps,
                          float* __restrict__ sz_out, float* __restrict__ szbuf)
{
    int id = blockIdx.x * blockDim.x + threadIdx.x;
    int b = id >> 6, l = id & 63;
    float mu = lz[b*128 + l];
    float lv = lz[b*128 + 64 + l];
    float v = mu + expf(0.5f * lv) * eps[b*64 + l];
    sz_out[id] = v;
    szbuf[id]  = v;
}

__global__ __launch_bounds__(256) void recs_k(const float* __restrict__ pred,
                                              float* __restrict__ out)
{
    long idx = (long)blockIdx.x * 256 + threadIdx.x;
    if (idx >= (long)BB*TT*VV) return;
    int v = (int)(idx % VV);
    int b = (int)(idx / ((long)VV * TT));
    out[idx] = pred[b*VV + v];
}

// ---------------- host orchestration ----------------
extern "C" void kernel_launch(void* const* d_in, const int* in_sizes, int n_in,
                              void* d_out, int out_size)
{
    const int*   actions = (const int*)  d_in[0];
    const int*   lengths = (const int*)  d_in[1];
    const float* gumbel  = (const float*)d_in[2];
    const float* eps_z   = (const float*)d_in[3];
    const float* embed   = (const float*)d_in[4];
    const float* Wx      = (const float*)d_in[5];
    const float* Wh      = (const float*)d_in[6];
    const float* b_lstm  = (const float*)d_in[7];
    const float* Wz1     = (const float*)d_in[8];
    const float* bz1     = (const float*)d_in[9];
    const float* Wz2     = (const float*)d_in[10];
    const float* bz2     = (const float*)d_in[11];
    const float* Wb1     = (const float*)d_in[12];
    const float* bb1     = (const float*)d_in[13];
    const float* Wb2     = (const float*)d_in[14];
    const float* bb2     = (const float*)d_in[15];
    const float* Wd1     = (const float*)d_in[16];
    const float* bd1     = (const float*)d_in[17];
    const float* Wd2     = (const float*)d_in[18];
    const float* bd2     = (const float*)d_in[19];
    float* out = (float*)d_out;

    float *p_embW, *p_mask, *p_logacc, *p_hid, *p_ro, *p_hz, *p_sz, *p_hd, *p_pred;
    cudaGetSymbolAddress((void**)&p_embW,   g_embW);
    cudaGetSymbolAddress((void**)&p_mask,   g_maskbuf);
    cudaGetSymbolAddress((void**)&p_logacc, g_logacc);
    cudaGetSymbolAddress((void**)&p_hid,    g_hid);
    cudaGetSymbolAddress((void**)&p_ro,     g_ro);
    cudaGetSymbolAddress((void**)&p_hz,     g_hz);
    cudaGetSymbolAddress((void**)&p_sz,     g_sz);
    cudaGetSymbolAddress((void**)&p_hd,     g_hd);
    cudaGetSymbolAddress((void**)&p_pred,   g_pred);

    cudaFuncSetAttribute(lstm_seg_k, cudaFuncAttributeMaxDynamicSharedMemorySize,
                         SMEM_BYTES);

    // embW = embed @ Wx   (500 x 2048, K=512)
    sgemm_k<<<dim3(32, 8, 1), 256>>>(embed, 512, Wx, 2048, p_embW, 2048,
                                     500, 2048, 512, nullptr, 0);
    pack_embW_k<<<500, 512>>>(b_lstm);
    pack_Wh2_k<<<512, 256>>>(Wh);
    zero1_k<<<64, 256>>>(p_logacc, BB*TT);

    for (int seg = 0; seg < SS; seg++) {
        float* enc = out + OFF_ENCS + (size_t)seg * BTH;
        const float* mptr = (seg == 0) ? nullptr : p_mask;

        lstm_seg_k<<<NBLK, NTHR, SMEM_BYTES>>>(actions, mptr, enc);

        if (seg < SS - 1) {
            sgemm_k<<<dim3(8, 256, 1), 256>>>(enc, 512, Wb1, 512, p_hid, 512,
                                              16384, 512, 512, bb1, 1);
            rowdot_k<<<2048, 256>>>(p_hid, Wb2, bb2, out + OFF_LOGB + (size_t)seg*BB*TT);
            softmax_mask_k<<<64, 256>>>(out + OFF_LOGB + (size_t)seg*BB*TT,
                                        gumbel + (size_t)seg*BB*TT,
                                        out + OFF_SB + (size_t)seg*BB*TT,
                                        out + OFF_MASKS + (size_t)seg*BB*TT,
                                        p_mask, p_logacc);
        } else {
            onehot_k<<<64, 256>>>(lengths, out + OFF_SB + (size_t)seg*BB*TT);
        }

        readout_k<<<64, 512>>>(enc, out + OFF_SB + (size_t)seg*BB*TT, p_ro);

        sgemm_k<<<dim3(8, 1, 1), 256>>>(p_ro, 512, Wz1, 512, p_hz, 512,
                                        64, 512, 512, bz1, 1);
        sgemm_k<<<dim3(2, 1, 1), 256>>>(p_hz, 512, Wz2, 128,
                                        out + OFF_LZ + (size_t)seg*BB*2*LL, 128,
                                        64, 128, 512, bz2, 0);
        samplez_k<<<16, 256>>>(out + OFF_LZ + (size_t)seg*BB*2*LL,
                               eps_z + (size_t)seg*BB*LL,
                               out + OFF_SZ + (size_t)seg*BB*LL, p_sz);
        sgemm_k<<<dim3(8, 1, 1), 256>>>(p_sz, 64, Wd1, 512, p_hd, 512,
                                        64, 512, 64, bd1, 1);
        sgemm_k<<<dim3(8, 1, 1), 256>>>(p_hd, 512, Wd2, 500, p_pred, 500,
                                        64, 500, 512, bd2, 0);
        recs_k<<<32000, 256>>>(p_pred, out + OFF_RECS + (size_t)seg*(size_t)BB*TT*VV);
    }
}

// round 15
// speedup vs baseline: 1.1450x; 1.0796x over previous
#include <cuda_runtime.h>
#include <cuda_bf16.h>
#include <math.h>

// Problem constants
#define BB 64
#define TT 256
#define HH 512
#define LL 64
#define VV 500
#define SS 3
#define NEG_INF -1000000000.0f
#define EPS_C 1e-17f

// Output section offsets (float32 elements)
#define BTH (64UL*256UL*512UL)                 // 8,388,608
#define OFF_ENCS  0UL
#define OFF_RECS  25165824UL                   // 3*BTH
#define OFF_MASKS 49741824UL                   // + 3*64*256*500
#define OFF_LOGB  49774592UL                   // + 2*16384
#define OFF_SB    49807360UL                   // + 2*16384
#define OFF_LZ    49856512UL                   // + 3*16384
#define OFF_SZ    49881088UL                   // + 3*8192

#define NBLK 128
#define NTHR 256
#define HROW 516                               // padded h row stride (floats)
#define WS_FLOATS 8192                         // [4 j][256 k2][8]
#define H_FLOATS  (64*HROW)                    // 33024
#define RB_LANE   20
#define RB_FLOATS (3*2*32*RB_LANE)             // 3840
#define SMEM_FLOATS (WS_FLOATS + H_FLOATS + RB_FLOATS)   // 45056
#define SMEM_BYTES  (SMEM_FLOATS*4)            // 180224 -> 1 block/SM

// -------- device scratch (no allocation allowed) --------
__device__ float g_embW[500*2048];         // embed @ Wx
__device__ float g_embWpack[500*512*4];    // [a][j][i,f,g,o] (+bias folded)
__device__ float g_Wpack2[512*256*8];      // [j][k2][i0,i1,f0,f1,g0,g1,o0,o1]
__device__ float g_hA[64*512];
__device__ float g_hB[64*512];
__device__ float g_maskbuf[64*256];
__device__ float g_logacc[64*256];
__device__ float g_hid[16384*512];
__device__ float g_ro[64*512];
__device__ float g_hz[64*512];
__device__ float g_sz[64*64];
__device__ float g_hd[64*512];
__device__ float g_pred[64*500];

// tree-barrier state: counters self-reset; flag monotonic => replay-safe
__device__ unsigned g_leaf[16*32];             // 16 leaves, 128B apart
__device__ unsigned g_root;
__device__ volatile unsigned g_flag2;

// ---------------- helpers ----------------
__device__ __forceinline__ void ffma2(unsigned long long& d,
                                      unsigned long long a,
                                      unsigned long long b) {
    asm("fma.rn.f32x2 %0, %1, %2, %0;" : "+l"(d) : "l"(a), "l"(b));
}
__device__ __forceinline__ float lh(unsigned long long v) {
    return __uint_as_float((unsigned)v) + __uint_as_float((unsigned)(v >> 32));
}
__device__ __forceinline__ float sigf(float x) { return 1.f / (1.f + expf(-x)); }

struct ull2 { unsigned long long x, y; };

__device__ __forceinline__ void cp16(float* s, const float* g) {
    unsigned sa = (unsigned)__cvta_generic_to_shared(s);
    asm volatile("cp.async.cg.shared.global [%0], [%1], 16;" :: "r"(sa), "l"(g));
}
__device__ __forceinline__ void cp_commit() {
    asm volatile("cp.async.commit_group;" ::: "memory");
}
template <int N>
__device__ __forceinline__ void cp_waitg() {
    asm volatile("cp.async.wait_group %0;" :: "n"(N) : "memory");
}

// tid0-only: tree arrive (16 leaves x 8 blocks, then root of 16)
__device__ __forceinline__ void tree_arrive(unsigned target) {
    int leaf = (blockIdx.x >> 3) << 5;         // *32 padding
    unsigned old = atomicAdd(&g_leaf[leaf], 1);
    if (old == 7) {
        g_leaf[leaf] = 0;                      // safe: next use is after release
        unsigned r = atomicAdd(&g_root, 1);
        if (r == 15) {
            g_root = 0;
            __threadfence();
            g_flag2 = target;
        }
    }
}

// ---------------- persistent masked-LSTM segment kernel ----------------
// 128 blocks x 256 threads. warp wid: jg = wid>>2 (2 j-pairs), kh = wid&3
// (k quarter). thread: 2 b (lane, lane+32) x 2 j (j0, j0+1) x 4 gates,
// 128-k quarter. kh 1..3 dump f32 partials to smem; kh 0 combines + gates.
__global__ __launch_bounds__(NTHR, 1) void lstm_seg_k(
    const int* __restrict__ actions,
    const float* __restrict__ maskp,   // nullptr for seg 0
    float* __restrict__ enc)
{
    extern __shared__ float smem[];
    float* ws = smem;                       // [4 j][256 k2][8]
    float* hs = smem + WS_FLOATS;           // [64][HROW]
    float* rb = hs + H_FLOATS;              // [3 kh][2 jg][32 lane][RB_LANE]

    const int tid  = threadIdx.x;
    const int lane = tid & 31;
    const int wid  = tid >> 5;
    const int jg   = wid >> 2;
    const int kh   = wid & 3;
    const int j0   = (blockIdx.x << 2) + (jg << 1);
    const int b1   = lane;
    const int b2   = lane + 32;

    // stage this block's Wh pack (constant across steps)
    {
        const float4* src = (const float4*)(g_Wpack2 + (size_t)blockIdx.x * 8192);
        float4* dst = (float4*)ws;
#pragma unroll
        for (int i = tid; i < 2048; i += NTHR) dst[i] = src[i];
    }
    __syncthreads();

    unsigned barBase = g_flag2;             // stable at kernel entry
    const int useMask = (maskp != nullptr);
    const float* wj0 = ws + ((jg << 1) << 11) + (kh << 9);   // j0, k-quarter
    const float* wj1 = wj0 + 2048;                            // j0+1
    const float* hp1 = hs + b1 * HROW + (kh << 7);
    const float* hp2 = hs + b2 * HROW + (kh << 7);
    float* myrb = rb + ((((kh - 1) << 1) + jg) * 32 + lane) * RB_LANE;  // kh>=1
    float c00 = 0.f, c01 = 0.f, c10 = 0.f, c11 = 0.f;   // [b][j]

    for (int t = 0; t < TT; t++) {
        // prefetch step inputs (kh0 warps only) — hidden under the k loop
        float4 x10, x11, x20, x21;
        float m1 = 1.f, m2 = 1.f;
        if (kh == 0) {
            int act1 = actions[b1 * TT + t];
            int act2 = actions[b2 * TT + t];
            const float4* e1 = (const float4*)(g_embWpack + (((size_t)act1 << 9) + j0) * 4);
            const float4* e2 = (const float4*)(g_embWpack + (((size_t)act2 << 9) + j0) * 4);
            x10 = e1[0]; x11 = e1[1];
            x20 = e2[0]; x21 = e2[1];
            if (useMask) { m1 = maskp[b1 * TT + t]; m2 = maskp[b2 * TT + t]; }
        }

        unsigned long long a0=0,a1=0,a2=0,a3=0,a4=0,a5=0,a6=0,a7=0;
        unsigned long long a8=0,a9=0,a10=0,a11=0,a12=0,a13=0,a14=0,a15=0;

        if (t > 0) {
            const float* cur = (t & 1) ? g_hA : g_hB;   // h(t-1)
#pragma unroll
            for (int it = 0; it < 32; it++) {
                int i = tid + (it << 8);
                int r = i >> 7;
                int q = i & 127;
                cp16(hs + r * HROW + (q << 2), cur + (r << 9) + (q << 2));
            }
            cp_commit();
            cp_waitg<0>();
            __syncthreads();

#pragma unroll 8
            for (int k4 = 0; k4 < 32; k4++) {
                ull2 ha = *(const ull2*)(hp1 + (k4 << 2));
                ull2 hb = *(const ull2*)(hp2 + (k4 << 2));
                const float* wk0 = wj0 + (k4 << 4);
                const float* wk1 = wj1 + (k4 << 4);
                ull2 wA0 = *(const ull2*)(wk0);
                ull2 wB0 = *(const ull2*)(wk0 + 4);
                ull2 wC0 = *(const ull2*)(wk0 + 8);
                ull2 wD0 = *(const ull2*)(wk0 + 12);
                ull2 wA1 = *(const ull2*)(wk1);
                ull2 wB1 = *(const ull2*)(wk1 + 4);
                ull2 wC1 = *(const ull2*)(wk1 + 8);
                ull2 wD1 = *(const ull2*)(wk1 + 12);

                // b1 j0
                ffma2(a0, ha.x, wA0.x); ffma2(a1, ha.x, wA0.y);
                ffma2(a2, ha.x, wB0.x); ffma2(a3, ha.x, wB0.y);
                ffma2(a0, ha.y, wC0.x); ffma2(a1, ha.y, wC0.y);
                ffma2(a2, ha.y, wD0.x); ffma2(a3, ha.y, wD0.y);
                // b1 j1
                ffma2(a4, ha.x, wA1.x); ffma2(a5, ha.x, wA1.y);
                ffma2(a6, ha.x, wB1.x); ffma2(a7, ha.x, wB1.y);
                ffma2(a4, ha.y, wC1.x); ffma2(a5, ha.y, wC1.y);
                ffma2(a6, ha.y, wD1.x); ffma2(a7, ha.y, wD1.y);
                // b2 j0
                ffma2(a8, hb.x, wA0.x);  ffma2(a9, hb.x, wA0.y);
                ffma2(a10, hb.x, wB0.x); ffma2(a11, hb.x, wB0.y);
                ffma2(a8, hb.y, wC0.x);  ffma2(a9, hb.y, wC0.y);
                ffma2(a10, hb.y, wD0.x); ffma2(a11, hb.y, wD0.y);
                // b2 j1
                ffma2(a12, hb.x, wA1.x); ffma2(a13, hb.x, wA1.y);
                ffma2(a14, hb.x, wB1.x); ffma2(a15, hb.x, wB1.y);
                ffma2(a12, hb.y, wC1.x); ffma2(a13, hb.y, wC1.y);
                ffma2(a14, hb.y, wD1.x); ffma2(a15, hb.y, wD1.y);
            }

            if (kh) {   // dump reduced partials
                float4* p = (float4*)myrb;
                p[0] = make_float4(lh(a0),  lh(a1),  lh(a2),  lh(a3));
                p[1] = make_float4(lh(a4),  lh(a5),  lh(a6),  lh(a7));
                p[2] = make_float4(lh(a8),  lh(a9),  lh(a10), lh(a11));
                p[3] = make_float4(lh(a12), lh(a13), lh(a14), lh(a15));
            }
            __syncthreads();
        }

        float h00, h01, h10, h11;
        if (kh == 0) {
            float z[16];
            if (t > 0) {
                z[0]=lh(a0);  z[1]=lh(a1);  z[2]=lh(a2);  z[3]=lh(a3);
                z[4]=lh(a4);  z[5]=lh(a5);  z[6]=lh(a6);  z[7]=lh(a7);
                z[8]=lh(a8);  z[9]=lh(a9);  z[10]=lh(a10); z[11]=lh(a11);
                z[12]=lh(a12); z[13]=lh(a13); z[14]=lh(a14); z[15]=lh(a15);
#pragma unroll
                for (int s = 0; s < 3; s++) {
                    const float4* q = (const float4*)(rb + (((s << 1) + jg) * 32 + lane) * RB_LANE);
                    float4 r0 = q[0], r1 = q[1], r2 = q[2], r3 = q[3];
                    z[0]+=r0.x; z[1]+=r0.y; z[2]+=r0.z; z[3]+=r0.w;
                    z[4]+=r1.x; z[5]+=r1.y; z[6]+=r1.z; z[7]+=r1.w;
                    z[8]+=r2.x; z[9]+=r2.y; z[10]+=r2.z; z[11]+=r2.w;
                    z[12]+=r3.x; z[13]+=r3.y; z[14]+=r3.z; z[15]+=r3.w;
                }
            } else {
#pragma unroll
                for (int i = 0; i < 16; i++) z[i] = 0.f;
            }
            z[0]+=x10.x; z[1]+=x10.y; z[2]+=x10.z; z[3]+=x10.w;
            z[4]+=x11.x; z[5]+=x11.y; z[6]+=x11.z; z[7]+=x11.w;
            z[8]+=x20.x; z[9]+=x20.y; z[10]+=x20.z; z[11]+=x20.w;
            z[12]+=x21.x; z[13]+=x21.y; z[14]+=x21.z; z[15]+=x21.w;

            float cn00 = sigf(z[1])  * c00 + sigf(z[0])  * tanhf(z[2]);
            h00 = sigf(z[3])  * tanhf(cn00);
            float cn01 = sigf(z[5])  * c01 + sigf(z[4])  * tanhf(z[6]);
            h01 = sigf(z[7])  * tanhf(cn01);
            float cn10 = sigf(z[9])  * c10 + sigf(z[8])  * tanhf(z[10]);
            h10 = sigf(z[11]) * tanhf(cn10);
            float cn11 = sigf(z[13]) * c11 + sigf(z[12]) * tanhf(z[14]);
            h11 = sigf(z[15]) * tanhf(cn11);

            c00 = m1 * cn00; c01 = m1 * cn01;
            c10 = m2 * cn10; c11 = m2 * cn11;

            float* nxt = (t & 1) ? g_hB : g_hA;
            *(float2*)(nxt + (b1 << 9) + j0) = make_float2(m1 * h00, m1 * h01);
            *(float2*)(nxt + (b2 << 9) + j0) = make_float2(m2 * h10, m2 * h11);
            __threadfence();
        }
        __syncthreads();

        if (t < TT - 1 && tid == 0) tree_arrive(barBase + t + 1);

        if (kh == 0) {   // outputs overlap the barrier wait
            *(float2*)(enc + ((size_t)b1 * TT + t) * HH + j0) = make_float2(h00, h01);
            *(float2*)(enc + ((size_t)b2 * TT + t) * HH + j0) = make_float2(h10, h11);
        }

        if (t < TT - 1) {
            if (tid == 0) {
                unsigned target = barBase + t + 1;
                while ((int)(g_flag2 - target) < 0) { }
                __threadfence();
            }
            __syncthreads();
        }
    }
}

// ---------------- pack kernels ----------------
__global__ void pack_embW_k(const float* __restrict__ b_lstm) {
    int a = blockIdx.x;         // 0..499
    int j = threadIdx.x;        // 0..511
    float4 v;
    v.x = g_embW[(size_t)a*2048 +        j] + b_lstm[j];
    v.y = g_embW[(size_t)a*2048 +  512 + j] + b_lstm[512 + j];
    v.z = g_embW[(size_t)a*2048 + 1024 + j] + b_lstm[1024 + j];
    v.w = g_embW[(size_t)a*2048 + 1536 + j] + b_lstm[1536 + j];
    *(float4*)(g_embWpack + ((size_t)a*512 + j)*4) = v;
}

// pack Wh into [j][k2][i0,i1,f0,f1,g0,g1,o0,o1]
__global__ void pack_Wh2_k(const float* __restrict__ Wh) {
    int idx = blockIdx.x * blockDim.x + threadIdx.x;   // 131072
    if (idx >= 512*256) return;
    int j  = idx >> 8;
    int k2 = idx & 255;
    float v[8];
#pragma unroll
    for (int g = 0; g < 4; g++) {
#pragma unroll
        for (int p = 0; p < 2; p++)
            v[g*2 + p] = Wh[(size_t)(2*k2 + p)*2048 + g*512 + j];
    }
    float4* dst = (float4*)(g_Wpack2 + ((size_t)j*256 + k2)*8);
    dst[0] = make_float4(v[0], v[1], v[2], v[3]);
    dst[1] = make_float4(v[4], v[5], v[6], v[7]);
}

// ---------------- generic tiled SGEMM ----------------
#define BM 64
#define BN 64
#define BKT 32
__global__ __launch_bounds__(256) void sgemm_k(
    const float* __restrict__ A, int lda,
    const float* __restrict__ B, int ldb,
    float* __restrict__ C, int ldc,
    int M, int N, int K,
    const float* __restrict__ bias, int relu)
{
    __shared__ float As[BKT][BM + 1];
    __shared__ float Bs[BKT][BN];

    int m0 = blockIdx.y * BM;
    int n0 = blockIdx.x * BN;
    int tid = threadIdx.x;
    int tx = tid & 15;
    int ty = tid >> 4;

    float acc[4][4];
#pragma unroll
    for (int i = 0; i < 4; i++)
#pragma unroll
        for (int jq = 0; jq < 4; jq++) acc[i][jq] = 0.f;

    for (int k0 = 0; k0 < K; k0 += BKT) {
#pragma unroll
        for (int i = 0; i < (BM*BKT)/256; i++) {
            int idx = tid + i*256;
            int m  = idx >> 5;
            int kk = idx & 31;
            int gm = m0 + m;
            As[kk][m] = (gm < M) ? A[(size_t)gm*lda + k0 + kk] : 0.f;
        }
#pragma unroll
        for (int i = 0; i < (BKT*BN)/256; i++) {
            int idx = tid + i*256;
            int kk = idx >> 6;
            int n  = idx & 63;
            int gn = n0 + n;
            Bs[kk][n] = (gn < N) ? B[(size_t)(k0+kk)*ldb + gn] : 0.f;
        }
        __syncthreads();
#pragma unroll
        for (int kk = 0; kk < BKT; kk++) {
            float a0 = As[kk][ty*4+0];
            float a1 = As[kk][ty*4+1];
            float a2 = As[kk][ty*4+2];
            float a3 = As[kk][ty*4+3];
            float4 b4 = *(const float4*)&Bs[kk][tx*4];
            acc[0][0] += a0*b4.x; acc[0][1] += a0*b4.y; acc[0][2] += a0*b4.z; acc[0][3] += a0*b4.w;
            acc[1][0] += a1*b4.x; acc[1][1] += a1*b4.y; acc[1][2] += a1*b4.z; acc[1][3] += a1*b4.w;
            acc[2][0] += a2*b4.x; acc[2][1] += a2*b4.y; acc[2][2] += a2*b4.z; acc[2][3] += a2*b4.w;
            acc[3][0] += a3*b4.x; acc[3][1] += a3*b4.y; acc[3][2] += a3*b4.z; acc[3][3] += a3*b4.w;
        }
        __syncthreads();
    }

#pragma unroll
    for (int i = 0; i < 4; i++) {
        int gm = m0 + ty*4 + i;
        if (gm >= M) continue;
#pragma unroll
        for (int jq = 0; jq < 4; jq++) {
            int gn = n0 + tx*4 + jq;
            if (gn >= N) continue;
            float v = acc[i][jq];
            if (bias) v += bias[gn];
            if (relu) v = fmaxf(v, 0.f);
            C[(size_t)gm*ldc + gn] = v;
        }
    }
}

// ---------------- small helpers ----------------
__global__ void zero1_k(float* a, int n) {
    int i = blockIdx.x * blockDim.x + threadIdx.x;
    if (i < n) a[i] = 0.f;
}

__global__ __launch_bounds__(256) void rowdot_k(
    const float* __restrict__ hid, const float* __restrict__ Wb2,
    const float* __restrict__ bb2, float* __restrict__ logits_out)
{
    int row  = blockIdx.x * 8 + (threadIdx.x >> 5);
    int lane = threadIdx.x & 31;
    const float* hr = hid + (size_t)row * 512;
    float acc = 0.f;
#pragma unroll
    for (int i = lane; i < 512; i += 32) acc += hr[i] * Wb2[i];
#pragma unroll
    for (int o = 16; o > 0; o >>= 1) acc += __shfl_down_sync(0xffffffffu, acc, o);
    if (lane == 0) {
        float v = acc + bb2[0];
        if ((row & 255) == 0) v = NEG_INF;
        logits_out[row] = v;
    }
}

__global__ __launch_bounds__(256) void softmax_mask_k(
    const float* __restrict__ logits, const float* __restrict__ gumbel,
    float* __restrict__ sb_out, float* __restrict__ mask_out,
    float* __restrict__ maskbuf, float* __restrict__ logacc)
{
    int b = blockIdx.x;
    int t = threadIdx.x;
    __shared__ float sh[256];

    float x = logits[b*TT + t] + gumbel[b*TT + t];
    sh[t] = x; __syncthreads();
    for (int s = 128; s > 0; s >>= 1) { if (t < s) sh[t] = fmaxf(sh[t], sh[t+s]); __syncthreads(); }
    float mx = sh[0]; __syncthreads();

    float e = expf(x - mx);
    sh[t] = e; __syncthreads();
    for (int s = 128; s > 0; s >>= 1) { if (t < s) sh[t] += sh[t+s]; __syncthreads(); }
    float sum = sh[0]; __syncthreads();

    float p = e / sum;
    sb_out[b*TT + t] = p;

    sh[t] = p; __syncthreads();
    for (int off = 1; off < 256; off <<= 1) {
        float v = (t >= off) ? sh[t - off] : 0.f;
        __syncthreads();
        sh[t] += v;
        __syncthreads();
    }
    float cum = sh[t];
    float la = logacc[b*TT + t] + logf(cum + EPS_C);
    logacc[b*TT + t] = la;
    float m = expf(la);
    maskbuf[b*TT + t] = m;
    mask_out[b*TT + t] = m;
}

__global__ void onehot_k(const int* __restrict__ lengths, float* __restrict__ sb_out) {
    int b = blockIdx.x, t = threadIdx.x;
    sb_out[b*TT + t] = (t == lengths[b] - 1) ? 1.f : 0.f;
}

__global__ __launch_bounds__(512) void readout_k(
    const float* __restrict__ enc, const float* __restrict__ sb,
    float* __restrict__ ro)
{
    int b = blockIdx.x;
    int h = threadIdx.x;
    __shared__ float s_sb[256];
    if (h < 256) s_sb[h] = sb[b*TT + h];
    __syncthreads();
    const float* e = enc + (size_t)b*TT*HH;
    float acc = 0.f;
    for (int t = 0; t < TT - 1; t++)
        acc += e[(size_t)t*HH + h] * s_sb[t + 1];
    ro[b*HH + h] = acc;
}

__global__ void samplez_k(const float* __restrict__ lz, const float* __restrict__ eps,
                          float* __restrict__ sz_out, float* __restrict__ szbuf)
{
    int id = blockIdx.x * blockDim.x + threadIdx.x;
    int b = id >> 6, l = id & 63;
    float mu = lz[b*128 + l];
    float lv = lz[b*128 + 64 + l];
    float v = mu + expf(0.5f * lv) * eps[b*64 + l];
    sz_out[id] = v;
    szbuf[id]  = v;
}

__global__ __launch_bounds__(256) void recs_k(const float* __restrict__ pred,
                                              float* __restrict__ out)
{
    long idx = (long)blockIdx.x * 256 + threadIdx.x;
    if (idx >= (long)BB*TT*VV) return;
    int v = (int)(idx % VV);
    int b = (int)(idx / ((long)VV * TT));
    out[idx] = pred[b*VV + v];
}

// ---------------- host orchestration ----------------
extern "C" void kernel_launch(void* const* d_in, const int* in_sizes, int n_in,
                              void* d_out, int out_size)
{
    const int*   actions = (const int*)  d_in[0];
    const int*   lengths = (const int*)  d_in[1];
    const float* gumbel  = (const float*)d_in[2];
    const float* eps_z   = (const float*)d_in[3];
    const float* embed   = (const float*)d_in[4];
    const float* Wx      = (const float*)d_in[5];
    const float* Wh      = (const float*)d_in[6];
    const float* b_lstm  = (const float*)d_in[7];
    const float* Wz1     = (const float*)d_in[8];
    const float* bz1     = (const float*)d_in[9];
    const float* Wz2     = (const float*)d_in[10];
    const float* bz2     = (const float*)d_in[11];
    const float* Wb1     = (const float*)d_in[12];
    const float* bb1     = (const float*)d_in[13];
    const float* Wb2     = (const float*)d_in[14];
    const float* bb2     = (const float*)d_in[15];
    const float* Wd1     = (const float*)d_in[16];
    const float* bd1     = (const float*)d_in[17];
    const float* Wd2     = (const float*)d_in[18];
    const float* bd2     = (const float*)d_in[19];
    float* out = (float*)d_out;

    float *p_embW, *p_mask, *p_logacc, *p_hid, *p_ro, *p_hz, *p_sz, *p_hd, *p_pred;
    cudaGetSymbolAddress((void**)&p_embW,   g_embW);
    cudaGetSymbolAddress((void**)&p_mask,   g_maskbuf);
    cudaGetSymbolAddress((void**)&p_logacc, g_logacc);
    cudaGetSymbolAddress((void**)&p_hid,    g_hid);
    cudaGetSymbolAddress((void**)&p_ro,     g_ro);
    cudaGetSymbolAddress((void**)&p_hz,     g_hz);
    cudaGetSymbolAddress((void**)&p_sz,     g_sz);
    cudaGetSymbolAddress((void**)&p_hd,     g_hd);
    cudaGetSymbolAddress((void**)&p_pred,   g_pred);

    cudaFuncSetAttribute(lstm_seg_k, cudaFuncAttributeMaxDynamicSharedMemorySize,
                         SMEM_BYTES);

    // embW = embed @ Wx   (500 x 2048, K=512)
    sgemm_k<<<dim3(32, 8, 1), 256>>>(embed, 512, Wx, 2048, p_embW, 2048,
                                     500, 2048, 512, nullptr, 0);
    pack_embW_k<<<500, 512>>>(b_lstm);
    pack_Wh2_k<<<512, 256>>>(Wh);
    zero1_k<<<64, 256>>>(p_logacc, BB*TT);

    for (int seg = 0; seg < SS; seg++) {
        float* enc = out + OFF_ENCS + (size_t)seg * BTH;
        const float* mptr = (seg == 0) ? nullptr : p_mask;

        lstm_seg_k<<<NBLK, NTHR, SMEM_BYTES>>>(actions, mptr, enc);

        if (seg < SS - 1) {
            sgemm_k<<<dim3(8, 256, 1), 256>>>(enc, 512, Wb1, 512, p_hid, 512,
                                              16384, 512, 512, bb1, 1);
            rowdot_k<<<2048, 256>>>(p_hid, Wb2, bb2, out + OFF_LOGB + (size_t)seg*BB*TT);
            softmax_mask_k<<<64, 256>>>(out + OFF_LOGB + (size_t)seg*BB*TT,
                                        gumbel + (size_t)seg*BB*TT,
                                        out + OFF_SB + (size_t)seg*BB*TT,
                                        out + OFF_MASKS + (size_t)seg*BB*TT,
                                        p_mask, p_logacc);
        } else {
            onehot_k<<<64, 256>>>(lengths, out + OFF_SB + (size_t)seg*BB*TT);
        }

        readout_k<<<64, 512>>>(enc, out + OFF_SB + (size_t)seg*BB*TT, p_ro);

        sgemm_k<<<dim3(8, 1, 1), 256>>>(p_ro, 512, Wz1, 512, p_hz, 512,
                                        64, 512, 512, bz1, 1);
        sgemm_k<<<dim3(2, 1, 1), 256>>>(p_hz, 512, Wz2, 128,
                                        out + OFF_LZ + (size_t)seg*BB*2*LL, 128,
                                        64, 128, 512, bz2, 0);
        samplez_k<<<16, 256>>>(out + OFF_LZ + (size_t)seg*BB*2*LL,
                               eps_z + (size_t)seg*BB*LL,
                               out + OFF_SZ + (size_t)seg*BB*LL, p_sz);
        sgemm_k<<<dim3(8, 1, 1), 256>>>(p_sz, 64, Wd1, 512, p_hd, 512,
                                        64, 512, 64, bd1, 1);
        sgemm_k<<<dim3(8, 1, 1), 256>>>(p_hd, 512, Wd2, 500, p_pred, 500,
                                        64, 500, 512, bd2, 0);
        recs_k<<<32000, 256>>>(p_pred, out + OFF_RECS + (size_t)seg*(size_t)BB*TT*VV);
    }
}

// round 17
// speedup vs baseline: 1.3143x; 1.1478x over previous
#include <cuda_runtime.h>
#include <cuda_bf16.h>
#include <math.h>

// Problem constants
#define BB 64
#define TT 256
#define HH 512
#define LL 64
#define VV 500
#define SS 3
#define NEG_INF -1000000000.0f
#define EPS_C 1e-17f

// Output section offsets (float32 elements)
#define BTH (64UL*256UL*512UL)                 // 8,388,608
#define OFF_ENCS  0UL
#define OFF_RECS  25165824UL                   // 3*BTH
#define OFF_MASKS 49741824UL                   // + 3*64*256*500
#define OFF_LOGB  49774592UL                   // + 2*16384
#define OFF_SB    49807360UL                   // + 2*16384
#define OFF_LZ    49856512UL                   // + 3*16384
#define OFF_SZ    49881088UL                   // + 3*8192

#define NBLK 128
#define NTHR 256
#define HROW 516                               // padded h row stride (floats)
#define MB_FLOATS 4                            // mbarrier slot (16B)
#define WS_FLOATS 8192                         // [4 j][256 k2][8]
#define H_FLOATS  (64*HROW)                    // 33024
#define RB_LANE   20
#define RB_FLOATS (3*2*32*RB_LANE)             // 3840
#define SMEM_FLOATS (MB_FLOATS + WS_FLOATS + H_FLOATS + RB_FLOATS)   // 45060
#define SMEM_BYTES  (SMEM_FLOATS*4)            // 180240 -> 1 block/SM

// -------- device scratch (no allocation allowed) --------
__device__ float g_embW[500*2048];         // embed @ Wx
__device__ float g_embWpack[500*512*4];    // [a][j][i,f,g,o] (+bias folded)
__device__ float g_Wpack2[512*256*8];      // [j][k2][i0,i1,f0,f1,g0,g1,o0,o1]
__device__ float g_hA[64*512];
__device__ float g_hB[64*512];
__device__ float g_maskbuf[64*256];
__device__ float g_logacc[64*256];
__device__ float g_hid[16384*512];
__device__ float g_ro[64*512];
__device__ float g_hz[64*512];
__device__ float g_sz[64*64];
__device__ float g_hd[64*512];
__device__ float g_pred[64*500];

// tree-barrier state: counters self-reset; flag monotonic => replay-safe
__device__ unsigned g_leaf[16*32];             // 16 leaves, 128B apart
__device__ unsigned g_root;
__device__ volatile unsigned g_flag2;

// ---------------- helpers ----------------
__device__ __forceinline__ void ffma2(unsigned long long& d,
                                      unsigned long long a,
                                      unsigned long long b) {
    asm("fma.rn.f32x2 %0, %1, %2, %0;" : "+l"(d) : "l"(a), "l"(b));
}
__device__ __forceinline__ float lh(unsigned long long v) {
    return __uint_as_float((unsigned)v) + __uint_as_float((unsigned)(v >> 32));
}
__device__ __forceinline__ float sigf(float x) { return 1.f / (1.f + expf(-x)); }

struct ull2 { unsigned long long x, y; };

// ---- mbarrier + bulk copy ----
__device__ __forceinline__ void mb_init(unsigned a, unsigned cnt) {
    asm volatile("mbarrier.init.shared.b64 [%0], %1;" :: "r"(a), "r"(cnt) : "memory");
}
__device__ __forceinline__ void mb_expect(unsigned a, unsigned bytes) {
    asm volatile("mbarrier.arrive.expect_tx.shared.b64 _, [%0], %1;"
                 :: "r"(a), "r"(bytes) : "memory");
}
__device__ __forceinline__ void mb_wait(unsigned a, unsigned par) {
    unsigned done;
    asm volatile(
        "{\n\t.reg .pred p;\n\t"
        "mbarrier.try_wait.parity.acquire.cta.shared::cta.b64 p, [%1], %2;\n\t"
        "selp.b32 %0, 1, 0, p;\n\t}"
        : "=r"(done) : "r"(a), "r"(par) : "memory");
    while (!done) {
        asm volatile(
            "{\n\t.reg .pred p;\n\t"
            "mbarrier.try_wait.parity.acquire.cta.shared::cta.b64 p, [%1], %2;\n\t"
            "selp.b32 %0, 1, 0, p;\n\t}"
            : "=r"(done) : "r"(a), "r"(par) : "memory");
    }
}
__device__ __forceinline__ void fence_async() {
    asm volatile("fence.proxy.async.shared::cta;" ::: "memory");
}
__device__ __forceinline__ void bulkcp(unsigned sa, const float* g,
                                       unsigned bytes, unsigned mbar) {
    asm volatile(
        "cp.async.bulk.shared::cta.global.mbarrier::complete_tx::bytes "
        "[%0], [%1], %2, [%3];"
        :: "r"(sa), "l"(g), "r"(bytes), "r"(mbar) : "memory");
}

// tid0-only: tree arrive (16 leaves x 8 blocks, then root of 16)
__device__ __forceinline__ void tree_arrive(unsigned target) {
    int leaf = (blockIdx.x >> 3) << 5;         // *32 padding
    unsigned old = atomicAdd(&g_leaf[leaf], 1);
    if (old == 7) {
        g_leaf[leaf] = 0;                      // safe: next use is after release
        unsigned r = atomicAdd(&g_root, 1);
        if (r == 15) {
            g_root = 0;
            __threadfence();
            g_flag2 = target;
        }
    }
}

// ---------------- persistent masked-LSTM segment kernel ----------------
// 128 blocks x 256 threads. warp wid: jg = wid>>2 (2 j-pairs), kh = wid&3
// (k quarter). thread: 2 b (lane, lane+32) x 2 j (j0, j0+1) x 4 gates,
// 128-k quarter. kh 1..3 dump f32 partials to smem; kh 0 combines + gates.
__global__ __launch_bounds__(NTHR, 1) void lstm_seg_k(
    const int* __restrict__ actions,
    const float* __restrict__ maskp,   // nullptr for seg 0
    float* __restrict__ enc,
    int zeroLog)
{
    extern __shared__ float smem[];
    float* ws = smem + MB_FLOATS;           // [4 j][256 k2][8]
    float* hs = ws + WS_FLOATS;             // [64][HROW]
    float* rb = hs + H_FLOATS;              // [3 kh][2 jg][32 lane][RB_LANE]

    const unsigned mbar = (unsigned)__cvta_generic_to_shared(smem);
    const unsigned hs_sa = (unsigned)__cvta_generic_to_shared(hs);

    const int tid  = threadIdx.x;
    const int lane = tid & 31;
    const int wid  = tid >> 5;
    const int jg   = wid >> 2;
    const int kh   = wid & 3;
    const int j0   = (blockIdx.x << 2) + (jg << 1);
    const int b1   = lane;
    const int b2   = lane + 32;

    if (tid == 0) mb_init(mbar, 1);

    if (zeroLog) {
        int gi = blockIdx.x * NTHR + tid;
        if (gi < BB * TT) g_logacc[gi] = 0.f;
    }

    // stage this block's Wh pack (constant across steps)
    {
        const float4* src = (const float4*)(g_Wpack2 + (size_t)blockIdx.x * 8192);
        float4* dst = (float4*)ws;
#pragma unroll
        for (int i = tid; i < 2048; i += NTHR) dst[i] = src[i];
    }
    __syncthreads();

    unsigned barBase = g_flag2;             // stable at kernel entry
    const int useMask = (maskp != nullptr);
    const float* wj0 = ws + ((jg << 1) << 11) + (kh << 9);   // j0, k-quarter
    const float* wj1 = wj0 + 2048;                            // j0+1
    const float* hp1 = hs + b1 * HROW + (kh << 7);
    const float* hp2 = hs + b2 * HROW + (kh << 7);
    float* myrb = rb + ((((kh - 1) << 1) + jg) * 32 + lane) * RB_LANE;  // kh>=1
    float c00 = 0.f, c01 = 0.f, c10 = 0.f, c11 = 0.f;   // [b][j]

    for (int t = 0; t < TT; t++) {
        // prefetch step inputs (kh0 warps only) — hidden under the k loop
        float4 x10, x11, x20, x21;
        float m1 = 1.f, m2 = 1.f;
        if (kh == 0) {
            int act1 = actions[b1 * TT + t];
            int act2 = actions[b2 * TT + t];
            const float4* e1 = (const float4*)(g_embWpack + (((size_t)act1 << 9) + j0) * 4);
            const float4* e2 = (const float4*)(g_embWpack + (((size_t)act2 << 9) + j0) * 4);
            x10 = e1[0]; x11 = e1[1];
            x20 = e2[0]; x21 = e2[1];
            if (useMask) { m1 = maskp[b1 * TT + t]; m2 = maskp[b2 * TT + t]; }
        }

        unsigned long long a0=0,a1=0,a2=0,a3=0,a4=0,a5=0,a6=0,a7=0;
        unsigned long long a8=0,a9=0,a10=0,a11=0,a12=0,a13=0,a14=0,a15=0;

        if (t > 0) {
            const float* cur = (t & 1) ? g_hA : g_hB;   // h(t-1)
            // 64 bulk copies: one padded 2KB row each, issued by 64 threads
            if (tid < 64) {
                if (tid == 0) mb_expect(mbar, 64 * 2048);
                fence_async();
                bulkcp(hs_sa + (unsigned)tid * (HROW * 4), cur + (tid << 9),
                       2048, mbar);
            }
            mb_wait(mbar, (t - 1) & 1);

#pragma unroll 8
            for (int k4 = 0; k4 < 32; k4++) {
                ull2 ha = *(const ull2*)(hp1 + (k4 << 2));
                ull2 hb = *(const ull2*)(hp2 + (k4 << 2));
                const float* wk0 = wj0 + (k4 << 4);
                const float* wk1 = wj1 + (k4 << 4);
                ull2 wA0 = *(const ull2*)(wk0);
                ull2 wB0 = *(const ull2*)(wk0 + 4);
                ull2 wC0 = *(const ull2*)(wk0 + 8);
                ull2 wD0 = *(const ull2*)(wk0 + 12);
                ull2 wA1 = *(const ull2*)(wk1);
                ull2 wB1 = *(const ull2*)(wk1 + 4);
                ull2 wC1 = *(const ull2*)(wk1 + 8);
                ull2 wD1 = *(const ull2*)(wk1 + 12);

                // b1 j0
                ffma2(a0, ha.x, wA0.x); ffma2(a1, ha.x, wA0.y);
                ffma2(a2, ha.x, wB0.x); ffma2(a3, ha.x, wB0.y);
                ffma2(a0, ha.y, wC0.x); ffma2(a1, ha.y, wC0.y);
                ffma2(a2, ha.y, wD0.x); ffma2(a3, ha.y, wD0.y);
                // b1 j1
                ffma2(a4, ha.x, wA1.x); ffma2(a5, ha.x, wA1.y);
                ffma2(a6, ha.x, wB1.x); ffma2(a7, ha.x, wB1.y);
                ffma2(a4, ha.y, wC1.x); ffma2(a5, ha.y, wC1.y);
                ffma2(a6, ha.y, wD1.x); ffma2(a7, ha.y, wD1.y);
                // b2 j0
                ffma2(a8, hb.x, wA0.x);  ffma2(a9, hb.x, wA0.y);
                ffma2(a10, hb.x, wB0.x); ffma2(a11, hb.x, wB0.y);
                ffma2(a8, hb.y, wC0.x);  ffma2(a9, hb.y, wC0.y);
                ffma2(a10, hb.y, wD0.x); ffma2(a11, hb.y, wD0.y);
                // b2 j1
                ffma2(a12, hb.x, wA1.x); ffma2(a13, hb.x, wA1.y);
                ffma2(a14, hb.x, wB1.x); ffma2(a15, hb.x, wB1.y);
                ffma2(a12, hb.y, wC1.x); ffma2(a13, hb.y, wC1.y);
                ffma2(a14, hb.y, wD1.x); ffma2(a15, hb.y, wD1.y);
            }

            if (kh) {   // dump reduced partials
                float4* p = (float4*)myrb;
                p[0] = make_float4(lh(a0),  lh(a1),  lh(a2),  lh(a3));
                p[1] = make_float4(lh(a4),  lh(a5),  lh(a6),  lh(a7));
                p[2] = make_float4(lh(a8),  lh(a9),  lh(a10), lh(a11));
                p[3] = make_float4(lh(a12), lh(a13), lh(a14), lh(a15));
            }
            __syncthreads();
        }

        float h00, h01, h10, h11;
        if (kh == 0) {
            float z[16];
            if (t > 0) {
                z[0]=lh(a0);  z[1]=lh(a1);  z[2]=lh(a2);  z[3]=lh(a3);
                z[4]=lh(a4);  z[5]=lh(a5);  z[6]=lh(a6);  z[7]=lh(a7);
                z[8]=lh(a8);  z[9]=lh(a9);  z[10]=lh(a10); z[11]=lh(a11);
                z[12]=lh(a12); z[13]=lh(a13); z[14]=lh(a14); z[15]=lh(a15);
#pragma unroll
                for (int s = 0; s < 3; s++) {
                    const float4* q = (const float4*)(rb + (((s << 1) + jg) * 32 + lane) * RB_LANE);
                    float4 r0 = q[0], r1 = q[1], r2 = q[2], r3 = q[3];
                    z[0]+=r0.x; z[1]+=r0.y; z[2]+=r0.z; z[3]+=r0.w;
                    z[4]+=r1.x; z[5]+=r1.y; z[6]+=r1.z; z[7]+=r1.w;
                    z[8]+=r2.x; z[9]+=r2.y; z[10]+=r2.z; z[11]+=r2.w;
                    z[12]+=r3.x; z[13]+=r3.y; z[14]+=r3.z; z[15]+=r3.w;
                }
            } else {
#pragma unroll
                for (int i = 0; i < 16; i++) z[i] = 0.f;
            }
            z[0]+=x10.x; z[1]+=x10.y; z[2]+=x10.z; z[3]+=x10.w;
            z[4]+=x11.x; z[5]+=x11.y; z[6]+=x11.z; z[7]+=x11.w;
            z[8]+=x20.x; z[9]+=x20.y; z[10]+=x20.z; z[11]+=x20.w;
            z[12]+=x21.x; z[13]+=x21.y; z[14]+=x21.z; z[15]+=x21.w;

            float cn00 = sigf(z[1])  * c00 + sigf(z[0])  * tanhf(z[2]);
            h00 = sigf(z[3])  * tanhf(cn00);
            float cn01 = sigf(z[5])  * c01 + sigf(z[4])  * tanhf(z[6]);
            h01 = sigf(z[7])  * tanhf(cn01);
            float cn10 = sigf(z[9])  * c10 + sigf(z[8])  * tanhf(z[10]);
            h10 = sigf(z[11]) * tanhf(cn10);
            float cn11 = sigf(z[13]) * c11 + sigf(z[12]) * tanhf(z[14]);
            h11 = sigf(z[15]) * tanhf(cn11);

            c00 = m1 * cn00; c01 = m1 * cn01;
            c10 = m2 * cn10; c11 = m2 * cn11;

            float* nxt = (t & 1) ? g_hB : g_hA;
            *(float2*)(nxt + (b1 << 9) + j0) = make_float2(m1 * h00, m1 * h01);
            *(float2*)(nxt + (b2 << 9) + j0) = make_float2(m2 * h10, m2 * h11);
            __threadfence();
        }
        __syncthreads();

        if (t < TT - 1 && tid == 0) tree_arrive(barBase + t + 1);

        if (kh == 0) {   // outputs overlap the barrier wait
            *(float2*)(enc + ((size_t)b1 * TT + t) * HH + j0) = make_float2(h00, h01);
            *(float2*)(enc + ((size_t)b2 * TT + t) * HH + j0) = make_float2(h10, h11);
        }

        if (t < TT - 1) {
            if (tid == 0) {
                unsigned target = barBase + t + 1;
                while ((int)(g_flag2 - target) < 0) { }
                __threadfence();
            }
            __syncthreads();
        }
    }
}

// ---------------- pack kernels ----------------
__global__ void pack_embW_k(const float* __restrict__ b_lstm) {
    int a = blockIdx.x;         // 0..499
    int j = threadIdx.x;        // 0..511
    float4 v;
    v.x = g_embW[(size_t)a*2048 +        j] + b_lstm[j];
    v.y = g_embW[(size_t)a*2048 +  512 + j] + b_lstm[512 + j];
    v.z = g_embW[(size_t)a*2048 + 1024 + j] + b_lstm[1024 + j];
    v.w = g_embW[(size_t)a*2048 + 1536 + j] + b_lstm[1536 + j];
    *(float4*)(g_embWpack + ((size_t)a*512 + j)*4) = v;
}

// pack Wh into [j][k2][i0,i1,f0,f1,g0,g1,o0,o1]
__global__ void pack_Wh2_k(const float* __restrict__ Wh) {
    int idx = blockIdx.x * blockDim.x + threadIdx.x;   // 131072
    if (idx >= 512*256) return;
    int j  = idx >> 8;
    int k2 = idx & 255;
    float v[8];
#pragma unroll
    for (int g = 0; g < 4; g++) {
#pragma unroll
        for (int p = 0; p < 2; p++)
            v[g*2 + p] = Wh[(size_t)(2*k2 + p)*2048 + g*512 + j];
    }
    float4* dst = (float4*)(g_Wpack2 + ((size_t)j*256 + k2)*8);
    dst[0] = make_float4(v[0], v[1], v[2], v[3]);
    dst[1] = make_float4(v[4], v[5], v[6], v[7]);
}

// ---------------- generic tiled SGEMM ----------------
#define BM 64
#define BN 64
#define BKT 32
__global__ __launch_bounds__(256) void sgemm_k(
    const float* __restrict__ A, int lda,
    const float* __restrict__ B, int ldb,
    float* __restrict__ C, int ldc,
    int M, int N, int K,
    const float* __restrict__ bias, int relu)
{
    __shared__ float As[BKT][BM + 1];
    __shared__ float Bs[BKT][BN];

    int m0 = blockIdx.y * BM;
    int n0 = blockIdx.x * BN;
    int tid = threadIdx.x;
    int tx = tid & 15;
    int ty = tid >> 4;

    float acc[4][4];
#pragma unroll
    for (int i = 0; i < 4; i++)
#pragma unroll
        for (int jq = 0; jq < 4; jq++) acc[i][jq] = 0.f;

    for (int k0 = 0; k0 < K; k0 += BKT) {
#pragma unroll
        for (int i = 0; i < (BM*BKT)/256; i++) {
            int idx = tid + i*256;
            int m  = idx >> 5;
            int kk = idx & 31;
            int gm = m0 + m;
            As[kk][m] = (gm < M) ? A[(size_t)gm*lda + k0 + kk] : 0.f;
        }
#pragma unroll
        for (int i = 0; i < (BKT*BN)/256; i++) {
            int idx = tid + i*256;
            int kk = idx >> 6;
            int n  = idx & 63;
            int gn = n0 + n;
            Bs[kk][n] = (gn < N) ? B[(size_t)(k0+kk)*ldb + gn] : 0.f;
        }
        __syncthreads();
#pragma unroll
        for (int kk = 0; kk < BKT; kk++) {
            float a0 = As[kk][ty*4+0];
            float a1 = As[kk][ty*4+1];
            float a2 = As[kk][ty*4+2];
            float a3 = As[kk][ty*4+3];
            float4 b4 = *(const float4*)&Bs[kk][tx*4];
            acc[0][0] += a0*b4.x; acc[0][1] += a0*b4.y; acc[0][2] += a0*b4.z; acc[0][3] += a0*b4.w;
            acc[1][0] += a1*b4.x; acc[1][1] += a1*b4.y; acc[1][2] += a1*b4.z; acc[1][3] += a1*b4.w;
            acc[2][0] += a2*b4.x; acc[2][1] += a2*b4.y; acc[2][2] += a2*b4.z; acc[2][3] += a2*b4.w;
            acc[3][0] += a3*b4.x; acc[3][1] += a3*b4.y; acc[3][2] += a3*b4.z; acc[3][3] += a3*b4.w;
        }
        __syncthreads();
    }

#pragma unroll
    for (int i = 0; i < 4; i++) {
        int gm = m0 + ty*4 + i;
        if (gm >= M) continue;
#pragma unroll
        for (int jq = 0; jq < 4; jq++) {
            int gn = n0 + tx*4 + jq;
            if (gn >= N) continue;
            float v = acc[i][jq];
            if (bias) v += bias[gn];
            if (relu) v = fmaxf(v, 0.f);
            C[(size_t)gm*ldc + gn] = v;
        }
    }
}

// ---------------- small helpers ----------------
__global__ __launch_bounds__(256) void rowdot_k(
    const float* __restrict__ hid, const float* __restrict__ Wb2,
    const float* __restrict__ bb2, float* __restrict__ logits_out)
{
    int row  = blockIdx.x * 8 + (threadIdx.x >> 5);
    int lane = threadIdx.x & 31;
    const float* hr = hid + (size_t)row * 512;
    float acc = 0.f;
#pragma unroll
    for (int i = lane; i < 512; i += 32) acc += hr[i] * Wb2[i];
#pragma unroll
    for (int o = 16; o > 0; o >>= 1) acc += __shfl_down_sync(0xffffffffu, acc, o);
    if (lane == 0) {
        float v = acc + bb2[0];
        if ((row & 255) == 0) v = NEG_INF;
        logits_out[row] = v;
    }
}

__global__ __launch_bounds__(256) void softmax_mask_k(
    const float* __restrict__ logits, const float* __restrict__ gumbel,
    float* __restrict__ sb_out, float* __restrict__ mask_out,
    float* __restrict__ maskbuf, float* __restrict__ logacc)
{
    int b = blockIdx.x;
    int t = threadIdx.x;
    __shared__ float sh[256];

    float x = logits[b*TT + t] + gumbel[b*TT + t];
    sh[t] = x; __syncthreads();
    for (int s = 128; s > 0; s >>= 1) { if (t < s) sh[t] = fmaxf(sh[t], sh[t+s]); __syncthreads(); }
    float mx = sh[0]; __syncthreads();

    float e = expf(x - mx);
    sh[t] = e; __syncthreads();
    for (int s = 128; s > 0; s >>= 1) { if (t < s) sh[t] += sh[t+s]; __syncthreads(); }
    float sum = sh[0]; __syncthreads();

    float p = e / sum;
    sb_out[b*TT + t] = p;

    sh[t] = p; __syncthreads();
    for (int off = 1; off < 256; off <<= 1) {
        float v = (t >= off) ? sh[t - off] : 0.f;
        __syncthreads();
        sh[t] += v;
        __syncthreads();
    }
    float cum = sh[t];
    float la = logacc[b*TT + t] + logf(cum + EPS_C);
    logacc[b*TT + t] = la;
    float m = expf(la);
    maskbuf[b*TT + t] = m;
    mask_out[b*TT + t] = m;
}

__global__ void onehot_k(const int* __restrict__ lengths, float* __restrict__ sb_out) {
    int b = blockIdx.x, t = threadIdx.x;
    sb_out[b*TT + t] = (t == lengths[b] - 1) ? 1.f : 0.f;
}

__global__ __launch_bounds__(512) void readout_k(
    const float* __restrict__ enc, const float* __restrict__ sb,
    float* __restrict__ ro)
{
    int b = blockIdx.x;
    int h = threadIdx.x;
    __shared__ float s_sb[256];
    if (h < 256) s_sb[h] = sb[b*TT + h];
    __syncthreads();
    const float* e = enc + (size_t)b*TT*HH;
    float acc = 0.f;
    for (int t = 0; t < TT - 1; t++)
        acc += e[(size_t)t*HH + h] * s_sb[t + 1];
    ro[b*HH + h] = acc;
}

__global__ void samplez_k(const float* __restrict__ lz, const float* __restrict__ eps,
                          float* __restrict__ sz_out, float* __restrict__ szbuf)
{
    int id = blockIdx.x * blockDim.x + threadIdx.x;
    int b = id >> 6, l = id & 63;
    float mu = lz[b*128 + l];
    float lv = lz[b*128 + 64 + l];
    float v = mu + expf(0.5f * lv) * eps[b*64 + l];
    sz_out[id] = v;
    szbuf[id]  = v;
}

__global__ __launch_bounds__(256) void recs_k(const float* __restrict__ pred,
                                              float* __restrict__ out)
{
    long idx = (long)blockIdx.x * 256 + threadIdx.x;
    if (idx >= (long)BB*TT*VV) return;
    int v = (int)(idx % VV);
    int b = (int)(idx / ((long)VV * TT));
    out[idx] = pred[b*VV + v];
}

// ---------------- host orchestration ----------------
extern "C" void kernel_launch(void* const* d_in, const int* in_sizes, int n_in,
                              void* d_out, int out_size)
{
    const int*   actions = (const int*)  d_in[0];
    const int*   lengths = (const int*)  d_in[1];
    const float* gumbel  = (const float*)d_in[2];
    const float* eps_z   = (const float*)d_in[3];
    const float* embed   = (const float*)d_in[4];
    const float* Wx      = (const float*)d_in[5];
    const float* Wh      = (const float*)d_in[6];
    const float* b_lstm  = (const float*)d_in[7];
    const float* Wz1     = (const float*)d_in[8];
    const float* bz1     = (const float*)d_in[9];
    const float* Wz2     = (const float*)d_in[10];
    const float* bz2     = (const float*)d_in[11];
    const float* Wb1     = (const float*)d_in[12];
    const float* bb1     = (const float*)d_in[13];
    const float* Wb2     = (const float*)d_in[14];
    const float* bb2     = (const float*)d_in[15];
    const float* Wd1     = (const float*)d_in[16];
    const float* bd1     = (const float*)d_in[17];
    const float* Wd2     = (const float*)d_in[18];
    const float* bd2     = (const float*)d_in[19];
    float* out = (float*)d_out;

    float *p_embW, *p_mask, *p_logacc, *p_hid, *p_ro, *p_hz, *p_sz, *p_hd, *p_pred;
    cudaGetSymbolAddress((void**)&p_embW,   g_embW);
    cudaGetSymbolAddress((void**)&p_mask,   g_maskbuf);
    cudaGetSymbolAddress((void**)&p_logacc, g_logacc);
    cudaGetSymbolAddress((void**)&p_hid,    g_hid);
    cudaGetSymbolAddress((void**)&p_ro,     g_ro);
    cudaGetSymbolAddress((void**)&p_hz,     g_hz);
    cudaGetSymbolAddress((void**)&p_sz,     g_sz);
    cudaGetSymbolAddress((void**)&p_hd,     g_hd);
    cudaGetSymbolAddress((void**)&p_pred,   g_pred);

    cudaFuncSetAttribute(lstm_seg_k, cudaFuncAttributeMaxDynamicSharedMemorySize,
                         SMEM_BYTES);

    // embW = embed @ Wx   (500 x 2048, K=512)
    sgemm_k<<<dim3(32, 8, 1), 256>>>(embed, 512, Wx, 2048, p_embW, 2048,
                                     500, 2048, 512, nullptr, 0);
    pack_embW_k<<<500, 512>>>(b_lstm);
    pack_Wh2_k<<<512, 256>>>(Wh);

    for (int seg = 0; seg < SS; seg++) {
        float* enc = out + OFF_ENCS + (size_t)seg * BTH;
        const float* mptr = (seg == 0) ? nullptr : p_mask;

        lstm_seg_k<<<NBLK, NTHR, SMEM_BYTES>>>(actions, mptr, enc, seg == 0);

        if (seg < SS - 1) {
            sgemm_k<<<dim3(8, 256, 1), 256>>>(enc, 512, Wb1, 512, p_hid, 512,
                                              16384, 512, 512, bb1, 1);
            rowdot_k<<<2048, 256>>>(p_hid, Wb2, bb2, out + OFF_LOGB + (size_t)seg*BB*TT);
            softmax_mask_k<<<64, 256>>>(out + OFF_LOGB + (size_t)seg*BB*TT,
                                        gumbel + (size_t)seg*BB*TT,
                                        out + OFF_SB + (size_t)seg*BB*TT,
                                        out + OFF_MASKS + (size_t)seg*BB*TT,
                                        p_mask, p_logacc);
        } else {
            onehot_k<<<64, 256>>>(lengths, out + OFF_SB + (size_t)seg*BB*TT);
        }

        readout_k<<<64, 512>>>(enc, out + OFF_SB + (size_t)seg*BB*TT, p_ro);

        sgemm_k<<<dim3(8, 1, 1), 256>>>(p_ro, 512, Wz1, 512, p_hz, 512,
                                        64, 512, 512, bz1, 1);
        sgemm_k<<<dim3(2, 1, 1), 256>>>(p_hz, 512, Wz2, 128,
                                        out + OFF_LZ + (size_t)seg*BB*2*LL, 128,
                                        64, 128, 512, bz2, 0);
        samplez_k<<<16, 256>>>(out + OFF_LZ + (size_t)seg*BB*2*LL,
                               eps_z + (size_t)seg*BB*LL,
                               out + OFF_SZ + (size_t)seg*BB*LL, p_sz);
        sgemm_k<<<dim3(8, 1, 1), 256>>>(p_sz, 64, Wd1, 512, p_hd, 512,
                                        64, 512, 64, bd1, 1);
        sgemm_k<<<dim3(8, 1, 1), 256>>>(p_hd, 512, Wd2, 500, p_pred, 500,
                                        64, 500, 512, bd2, 0);
        recs_k<<<32000, 256>>>(p_pred, out + OFF_RECS + (size_t)seg*(size_t)BB*TT*VV);
    }
}